// round 6
// baseline (speedup 1.0000x reference)
#include <cuda_runtime.h>
#include <cuda_bf16.h>
#include <math.h>
#include <stdint.h>

// ---------------- problem constants ----------------
#define VSZ   128
#define V1SZ  129
#define HSZ   512
#define H4SZ  2048
#define ESZ   128
#define NEXN  4
#define LLEN  32
#define BSZ   512
#define TLEN  32
#define NB    (NEXN * BSZ)      // 2048
#define NT_ALL (TLEN * NB)      // 65536
#define NEGV  (-1e9f)

// ---------------- device scratch (allocation-free) ----------------
__device__ __nv_bfloat16 g_Hs[(size_t)LLEN * NB * HSZ];   // 64 MB encoder hiddens, time-major
__device__ __nv_bfloat16 g_Hd[(size_t)TLEN * NB * HSZ];   // 64 MB decoder hiddens, time-major
__device__ __nv_bfloat16 g_hbf[NB * HSZ];                 // h input for t=0 steps
__device__ float g_c[NB * HSZ];
__device__ __nv_bfloat16 g_ubf[(size_t)NT_ALL * HSZ];     // 64 MB u (bf16)
__device__ __nv_bfloat16 g_hcbf[(size_t)NT_ALL * 2 * HSZ];// 128 MB [h,ctx]
__device__ float g_fc[(size_t)NT_ALL * ESZ];              // 32 MB
__device__ float g_mask[NEXN * LLEN * BSZ];
__device__ int   g_idx[NB];
// permuted / converted weights
__device__ __nv_bfloat16 g_WhhPE[H4SZ * HSZ];             // gate-interleaved enc Whh (bf16)
__device__ __nv_bfloat16 g_WhhPD[H4SZ * HSZ];
__device__ float g_WihPE[H4SZ * V1SZ];
__device__ float g_WihPD[H4SZ * V1SZ];
__device__ float g_ebE[H4SZ];
__device__ float g_ebD[H4SZ];
__device__ __nv_bfloat16 g_Awb[HSZ * HSZ];
__device__ __nv_bfloat16 g_Wwb[ESZ * 2 * HSZ];

__device__ __forceinline__ float sigmoidf_(float x) { return 1.f / (1.f + expf(-x)); }

// ---------------- ptx helpers ----------------
__device__ __forceinline__ void cp_async16(uint32_t dst, const void* src) {
    asm volatile("cp.async.cg.shared.global [%0], [%1], 16;\n" :: "r"(dst), "l"(src));
}
__device__ __forceinline__ void cp_commit() { asm volatile("cp.async.commit_group;\n"); }
template<int N> __device__ __forceinline__ void cp_wait() {
    asm volatile("cp.async.wait_group %0;\n" :: "n"(N));
}
__device__ __forceinline__ void ldm_x4(uint32_t& r0, uint32_t& r1, uint32_t& r2, uint32_t& r3,
                                       uint32_t addr) {
    asm volatile("ldmatrix.sync.aligned.m8n8.x4.shared.b16 {%0,%1,%2,%3}, [%4];"
                 : "=r"(r0), "=r"(r1), "=r"(r2), "=r"(r3) : "r"(addr));
}

// ---------------- weight prep ----------------
__global__ void convert_bf16_kernel(const float* __restrict__ src,
                                    __nv_bfloat16* __restrict__ dst, int n) {
    int i = blockIdx.x * blockDim.x + threadIdx.x;
    if (i < n) dst[i] = __float2bfloat16_rn(src[i]);
}

// gate-interleave permutation: n' = 4h+gate  <-  orig = gate*H + h
__global__ void permute_lstm_weights_kernel(
    const float* __restrict__ Whh, const float* __restrict__ bih,
    const float* __restrict__ bhh, const float* __restrict__ Wih,
    __nv_bfloat16* __restrict__ WhhP, float* __restrict__ eb, float* __restrict__ WihP) {
    int np = blockIdx.x;                  // 0..2047
    int h = np >> 2, g = np & 3;
    int orig = g * HSZ + h;
    for (int k = threadIdx.x; k < HSZ; k += 256)
        WhhP[np * HSZ + k] = __float2bfloat16_rn(Whh[(size_t)orig * HSZ + k]);
    for (int v = threadIdx.x; v < V1SZ; v += 256)
        WihP[np * V1SZ + v] = Wih[(size_t)orig * V1SZ + v];
    if (threadIdx.x == 0) eb[np] = bih[orig] + bhh[orig];
}

// ---------------- init kernels ----------------
__global__ void init_hc_kernel(const float* __restrict__ h0, const float* __restrict__ c0) {
    int idx = blockIdx.x * blockDim.x + threadIdx.x;
    if (idx < NB * HSZ) {
        int hh = idx & (HSZ - 1);
        g_hbf[idx] = __float2bfloat16_rn(h0[hh]);
        g_c[idx] = c0[hh];
    }
}

__global__ void init_mask_kernel(const int* __restrict__ inputs) {
    int r = blockIdx.x * blockDim.x + threadIdx.x;
    if (r < NB) {
        int j = r / BSZ, b = r % BSZ;
        float a = 1.f;
        int cnt = 0;
        #pragma unroll
        for (int l = 0; l < LLEN; l++) {
            g_mask[(j * LLEN + l) * BSZ + b] = (a > 0.f) ? 0.f : NEGV;
            cnt += (a > 0.f) ? 1 : 0;
            a *= (inputs[(j * LLEN + l) * BSZ + b] != VSZ) ? 1.f : 0.f;
        }
        g_idx[r] = cnt - 1;
    }
}

// ================= fused GEMM + LSTM cell, single-wave tiling =================
// CTA tile 256x128, 8 warps as 4(m) x 2(n), warp tile 64x64. 3-stage cp.async.
// Grid: (H4SZ/128, NB/256) = (16, 8) = 128 CTAs = 1 wave.
// gates = A @ WhhP^T (+ eb + WihP[:,tok]); LSTM pointwise update in epilogue.
// tokmode: 0 = SOS (tok=VSZ); 1 = encoder; 2 = decoder
__global__ __launch_bounds__(256, 1)
void lstm_step_kernel(const __nv_bfloat16* __restrict__ A,
                      const __nv_bfloat16* __restrict__ Bw,
                      __nv_bfloat16* __restrict__ Hout,
                      const float* __restrict__ eb, const float* __restrict__ WihP,
                      const int* __restrict__ tokp, int tokmode) {
    constexpr int BM = 256, BN = 128, BK = 32, K = HSZ;
    constexpr int AST = 40;                       // 80B row stride, conflict-free ldmatrix
    constexpr int MT = 4, NTc = 8;                // warp tile 64x64
    constexpr int STAGE = (BM + BN) * AST;        // bf16 elems per stage
    constexpr int NSTAGE = 3;
    constexpr int NIT = K / BK;                   // 16

    extern __shared__ __nv_bfloat16 smd[];
    const uint32_t smbase = (uint32_t)__cvta_generic_to_shared(smd);

    const int tid = threadIdx.x;
    const int warp = tid >> 5, lane = tid & 31;
    const int wm = warp >> 1;                     // 0..3
    const int wn = warp & 1;                      // 0..1
    const int m0 = blockIdx.y * BM, n0 = blockIdx.x * BN;

    float acc[MT][NTc][4];
    #pragma unroll
    for (int mt = 0; mt < MT; mt++)
        #pragma unroll
        for (int nt = 0; nt < NTc; nt++)
            #pragma unroll
            for (int q = 0; q < 4; q++) acc[mt][nt][q] = 0.f;

    auto load_stage = [&](int it) {
        const int k0 = it * BK;
        const uint32_t base = smbase + (uint32_t)(it % NSTAGE) * STAGE * 2;
        #pragma unroll
        for (int ii = 0; ii < (BM + BN) * 4 / 256; ii++) {
            int c = tid + ii * 256;
            bool isB = c >= BM * 4;
            int cc = isB ? c - BM * 4 : c;
            int row = cc >> 2, part = cc & 3;
            const __nv_bfloat16* src = isB
                ? (Bw + (size_t)(n0 + row) * K + k0 + part * 8)
                : (A  + (size_t)(m0 + row) * K + k0 + part * 8);
            uint32_t dst = base + (uint32_t)(((isB ? BM + row : row) * AST + part * 8) * 2);
            cp_async16(dst, src);
        }
        cp_commit();
    };

    load_stage(0);
    load_stage(1);

    for (int it = 0; it < NIT; it++) {
        cp_wait<1>();
        __syncthreads();
        if (it + 2 < NIT) load_stage(it + 2);

        const uint32_t aBase = smbase + (uint32_t)(it % NSTAGE) * STAGE * 2;
        const uint32_t bBase = aBase + BM * AST * 2;

        #pragma unroll
        for (int kk = 0; kk < 2; kk++) {
            uint32_t a[MT][4];
            #pragma unroll
            for (int mt = 0; mt < MT; mt++) {
                int row = wm * 64 + mt * 16 + (lane & 15);
                int col = kk * 16 + (lane >> 4) * 8;
                ldm_x4(a[mt][0], a[mt][1], a[mt][2], a[mt][3],
                       aBase + (uint32_t)((row * AST + col) * 2));
            }
            uint32_t b[NTc][2];
            #pragma unroll
            for (int ntp = 0; ntp < NTc / 2; ntp++) {
                int row = wn * 64 + ntp * 16 + ((lane >> 4) << 3) + (lane & 7);
                int col = kk * 16 + ((lane >> 3) & 1) * 8;
                ldm_x4(b[2 * ntp][0], b[2 * ntp][1], b[2 * ntp + 1][0], b[2 * ntp + 1][1],
                       bBase + (uint32_t)((row * AST + col) * 2));
            }
            #pragma unroll
            for (int mt = 0; mt < MT; mt++)
                #pragma unroll
                for (int nt = 0; nt < NTc; nt++) {
                    asm volatile(
                        "mma.sync.aligned.m16n8k16.row.col.f32.bf16.bf16.f32 "
                        "{%0,%1,%2,%3}, {%4,%5,%6,%7}, {%8,%9}, {%0,%1,%2,%3};"
                        : "+f"(acc[mt][nt][0]), "+f"(acc[mt][nt][1]),
                          "+f"(acc[mt][nt][2]), "+f"(acc[mt][nt][3])
                        : "r"(a[mt][0]), "r"(a[mt][1]), "r"(a[mt][2]), "r"(a[mt][3]),
                          "r"(b[nt][0]), "r"(b[nt][1]));
                }
        }
        __syncthreads();
    }

    // -------- fused LSTM epilogue --------
    const unsigned FULL = 0xffffffffu;
    #pragma unroll
    for (int mt = 0; mt < MT; mt++) {
        int r_lo = m0 + wm * 64 + mt * 16 + (lane >> 2);
        int r_hi = r_lo + 8;
        int tok_lo = VSZ, tok_hi = VSZ;
        if (tokmode == 1) {
            tok_lo = tokp[(r_lo / BSZ) * (LLEN * BSZ) + (r_lo % BSZ)];
            tok_hi = tokp[(r_hi / BSZ) * (LLEN * BSZ) + (r_hi % BSZ)];
        } else if (tokmode == 2) {
            tok_lo = tokp[r_lo % BSZ];
            tok_hi = tokp[r_hi % BSZ];
        }
        #pragma unroll
        for (int nt = 0; nt < NTc; nt++) {
            int c0 = n0 + wn * 64 + nt * 8 + 2 * (lane & 3);
            float e0 = eb[c0], e1 = eb[c0 + 1];
            float v00 = acc[mt][nt][0] + e0 + WihP[(size_t)c0 * V1SZ + tok_lo];
            float v01 = acc[mt][nt][1] + e1 + WihP[(size_t)(c0 + 1) * V1SZ + tok_lo];
            float v10 = acc[mt][nt][2] + e0 + WihP[(size_t)c0 * V1SZ + tok_hi];
            float v11 = acc[mt][nt][3] + e1 + WihP[(size_t)(c0 + 1) * V1SZ + tok_hi];
            // lane-pair exchange: even q holds (i,f), odd q holds (g,o)
            float p00 = __shfl_xor_sync(FULL, v00, 1);
            float p01 = __shfl_xor_sync(FULL, v01, 1);
            float p10 = __shfl_xor_sync(FULL, v10, 1);
            float p11 = __shfl_xor_sync(FULL, v11, 1);
            if ((lane & 1) == 0) {
                int h = c0 >> 2;
                {
                    float cold = g_c[(size_t)r_lo * HSZ + h];
                    float c2 = sigmoidf_(v01) * cold + sigmoidf_(v00) * tanhf(p00);
                    float h2 = sigmoidf_(p01) * tanhf(c2);
                    g_c[(size_t)r_lo * HSZ + h] = c2;
                    Hout[(size_t)r_lo * HSZ + h] = __float2bfloat16_rn(h2);
                }
                {
                    float cold = g_c[(size_t)r_hi * HSZ + h];
                    float c2 = sigmoidf_(v11) * cold + sigmoidf_(v10) * tanhf(p10);
                    float h2 = sigmoidf_(p11) * tanhf(c2);
                    g_c[(size_t)r_hi * HSZ + h] = c2;
                    Hout[(size_t)r_hi * HSZ + h] = __float2bfloat16_rn(h2);
                }
            }
        }
    }
}

// ================= generic bf16 GEMM (tail, batched — unchanged from R5) =================
// MODE 0: f32 store; MODE 2: tanh(+b1) f32 store; MODE 4: bf16 store
template<int MODE>
__global__ __launch_bounds__(256)
void bf16_gemm_kernel(const __nv_bfloat16* __restrict__ A, const __nv_bfloat16* __restrict__ Bw,
                      void* __restrict__ Cv, int M, int N, int K,
                      const float* __restrict__ b1) {
    constexpr int BM = 128, BN = 128, BK = 32;
    constexpr int AST = 40;
    constexpr int MT = 2, NTc = 8;
    constexpr int STAGE = (BM + BN) * AST;

    __shared__ __nv_bfloat16 sm[2 * STAGE];
    const uint32_t smbase = (uint32_t)__cvta_generic_to_shared(sm);

    const int tid = threadIdx.x;
    const int warp = tid >> 5, lane = tid & 31;
    const int wm = warp >> 1;
    const int wn = warp & 1;
    const int m0 = blockIdx.y * BM, n0 = blockIdx.x * BN;
    const int NIT = K / BK;

    float acc[MT][NTc][4];
    #pragma unroll
    for (int mt = 0; mt < MT; mt++)
        #pragma unroll
        for (int nt = 0; nt < NTc; nt++)
            #pragma unroll
            for (int q = 0; q < 4; q++) acc[mt][nt][q] = 0.f;

    auto load_stage = [&](int it, int buf) {
        const int k0 = it * BK;
        const uint32_t base = smbase + (uint32_t)buf * STAGE * 2;
        #pragma unroll
        for (int c = tid; c < (BM + BN) * 4; c += 256) {
            bool isB = c >= BM * 4;
            int cc = isB ? c - BM * 4 : c;
            int row = cc >> 2, part = cc & 3;
            const __nv_bfloat16* src = isB
                ? (Bw + (size_t)(n0 + row) * K + k0 + part * 8)
                : (A  + (size_t)(m0 + row) * K + k0 + part * 8);
            uint32_t dst = base + (uint32_t)(((isB ? BM + row : row) * AST + part * 8) * 2);
            cp_async16(dst, src);
        }
    };

    load_stage(0, 0);
    cp_commit();

    for (int it = 0; it < NIT; it++) {
        if (it + 1 < NIT) { load_stage(it + 1, (it + 1) & 1); cp_commit(); cp_wait<1>(); }
        else              { cp_wait<0>(); }
        __syncthreads();

        const uint32_t aBase = smbase + (uint32_t)(it & 1) * STAGE * 2;
        const uint32_t bBase = aBase + BM * AST * 2;

        #pragma unroll
        for (int kk = 0; kk < 2; kk++) {
            uint32_t a[MT][4];
            #pragma unroll
            for (int mt = 0; mt < MT; mt++) {
                int row = wm * 32 + mt * 16 + (lane & 15);
                int col = kk * 16 + (lane >> 4) * 8;
                ldm_x4(a[mt][0], a[mt][1], a[mt][2], a[mt][3],
                       aBase + (uint32_t)((row * AST + col) * 2));
            }
            uint32_t b[NTc][2];
            #pragma unroll
            for (int ntp = 0; ntp < NTc / 2; ntp++) {
                int row = wn * 64 + ntp * 16 + ((lane >> 4) << 3) + (lane & 7);
                int col = kk * 16 + ((lane >> 3) & 1) * 8;
                ldm_x4(b[2 * ntp][0], b[2 * ntp][1], b[2 * ntp + 1][0], b[2 * ntp + 1][1],
                       bBase + (uint32_t)((row * AST + col) * 2));
            }
            #pragma unroll
            for (int mt = 0; mt < MT; mt++)
                #pragma unroll
                for (int nt = 0; nt < NTc; nt++) {
                    asm volatile(
                        "mma.sync.aligned.m16n8k16.row.col.f32.bf16.bf16.f32 "
                        "{%0,%1,%2,%3}, {%4,%5,%6,%7}, {%8,%9}, {%0,%1,%2,%3};"
                        : "+f"(acc[mt][nt][0]), "+f"(acc[mt][nt][1]),
                          "+f"(acc[mt][nt][2]), "+f"(acc[mt][nt][3])
                        : "r"(a[mt][0]), "r"(a[mt][1]), "r"(a[mt][2]), "r"(a[mt][3]),
                          "r"(b[nt][0]), "r"(b[nt][1]));
                }
        }
        __syncthreads();
    }

    float* Cf = (float*)Cv;
    __nv_bfloat16* Cb = (__nv_bfloat16*)Cv;
    #pragma unroll
    for (int mt = 0; mt < MT; mt++) {
        int r_lo = m0 + wm * 32 + mt * 16 + (lane >> 2);
        int r_hi = r_lo + 8;
        #pragma unroll
        for (int nt = 0; nt < NTc; nt++) {
            int c0 = n0 + wn * 64 + nt * 8 + 2 * (lane & 3);
            float v00 = acc[mt][nt][0], v01 = acc[mt][nt][1];
            float v10 = acc[mt][nt][2], v11 = acc[mt][nt][3];
            if (MODE == 2) {
                float bb0 = b1[c0], bb1 = b1[c0 + 1];
                v00 = tanhf(v00 + bb0); v01 = tanhf(v01 + bb1);
                v10 = tanhf(v10 + bb0); v11 = tanhf(v11 + bb1);
            }
            if (MODE == 4) {
                __nv_bfloat162 lo = __floats2bfloat162_rn(v00, v01);
                __nv_bfloat162 hi = __floats2bfloat162_rn(v10, v11);
                *(__nv_bfloat162*)&Cb[(size_t)r_lo * N + c0] = lo;
                *(__nv_bfloat162*)&Cb[(size_t)r_hi * N + c0] = hi;
            } else {
                Cf[(size_t)r_lo * N + c0] = v00;
                Cf[(size_t)r_lo * N + c0 + 1] = v01;
                Cf[(size_t)r_hi * N + c0] = v10;
                Cf[(size_t)r_hi * N + c0 + 1] = v11;
            }
        }
    }
}

// ---------------- gather final-hidden embedding, set decoder c0 ----------------
__global__ void gather_emb_kernel(const float* __restrict__ dec_c0) {
    int idx = blockIdx.x * blockDim.x + threadIdx.x;
    if (idx >= NB * HSZ) return;
    int r = idx >> 9;
    int hh = idx & (HSZ - 1);
    int li = g_idx[r];
    g_hbf[idx] = g_Hs[((size_t)li * NB + r) * HSZ + hh];
    g_c[idx] = dec_c0[hh];
}

// ---------------- batched attention over all 32 timesteps ----------------
__global__ __launch_bounds__(256) void attn_all_kernel() {
    __shared__ __nv_bfloat16 hs_s[LLEN * HSZ];   // 32 KB
    __shared__ float u_s[HSZ];
    __shared__ float sc[LLEN];
    __shared__ float mask_s[LLEN];

    const int r = blockIdx.x;
    const int j = r / BSZ;
    const int tid = threadIdx.x;
    const int warp = tid >> 5, lane = tid & 31;

    #pragma unroll
    for (int idx = tid; idx < LLEN * HSZ / 8; idx += 256) {
        int l = idx >> 6;
        int c8 = (idx & 63) * 8;
        uint4 v = *(const uint4*)&g_Hs[((size_t)l * NB + r) * HSZ + c8];
        *(uint4*)&hs_s[l * HSZ + c8] = v;
    }
    if (tid < LLEN) mask_s[tid] = g_mask[(j * LLEN + tid) * BSZ + (r % BSZ)];
    __syncthreads();

    for (int t = 0; t < TLEN; t++) {
        const size_t row = (size_t)t * NB + r;
        for (int k = tid; k < HSZ; k += 256)
            u_s[k] = __bfloat162float(g_ubf[row * HSZ + k]);
        __syncthreads();

        for (int l = warp; l < LLEN; l += 8) {
            float s = 0.f;
            for (int k = lane; k < HSZ; k += 32)
                s += __bfloat162float(hs_s[l * HSZ + k]) * u_s[k];
            #pragma unroll
            for (int off = 16; off > 0; off >>= 1) s += __shfl_down_sync(0xffffffffu, s, off);
            if (lane == 0) sc[l] = s + mask_s[l];
        }
        __syncthreads();

        if (warp == 0) {
            float v = sc[lane];
            float mx = v;
            #pragma unroll
            for (int off = 16; off > 0; off >>= 1) mx = fmaxf(mx, __shfl_xor_sync(0xffffffffu, mx, off));
            float e = expf(v - mx);
            float ssum = e;
            #pragma unroll
            for (int off = 16; off > 0; off >>= 1) ssum += __shfl_xor_sync(0xffffffffu, ssum, off);
            sc[lane] = e / ssum;
        }
        __syncthreads();

        __nv_bfloat16* hc = g_hcbf + row * (2 * HSZ);
        #pragma unroll
        for (int kq = 0; kq < 2; kq++) {
            int k = tid + kq * 256;
            float cx = 0.f;
            #pragma unroll
            for (int l = 0; l < LLEN; l++) cx += sc[l] * __bfloat162float(hs_s[l * HSZ + k]);
            hc[HSZ + k] = __float2bfloat16_rn(cx);
        }
        if (tid < 64) {
            uint4 v = *(const uint4*)&g_Hd[row * HSZ + tid * 8];
            *(uint4*)&hc[tid * 8] = v;
        }
        __syncthreads();
    }
}

// ---------------- pool + logits + log-softmax + score over all t ----------------
__global__ __launch_bounds__(256) void pool_score_all_kernel(
    const float* __restrict__ Vw, const float* __restrict__ Vb,
    const int* __restrict__ target, float* __restrict__ out) {
    extern __shared__ float dsm[];
    float* Vw_s = dsm;                 // [128][132] e-major, padded
    float* m_s  = dsm + ESZ * 132;
    float* lgs  = m_s + ESZ;
    __shared__ float red[2];

    const int b = blockIdx.x;
    const int tid = threadIdx.x;
    const int lane = tid & 31;

    for (int idx = tid; idx < V1SZ * ESZ; idx += 256) {
        int v = idx >> 7, e = idx & 127;
        Vw_s[e * 132 + v] = Vw[(size_t)v * ESZ + e];
    }
    __syncthreads();

    float score = 0.f, act = 1.f;
    for (int t = 0; t < TLEN; t++) {
        if (tid < ESZ) {
            const size_t base = ((size_t)t * NB + b) * ESZ + tid;
            float m = g_fc[base];
            #pragma unroll
            for (int jj = 1; jj < NEXN; jj++)
                m = fmaxf(m, g_fc[base + (size_t)jj * BSZ * ESZ]);
            m_s[tid] = m;
        }
        __syncthreads();

        if (tid < V1SZ) {
            float s = Vb[tid];
            #pragma unroll 8
            for (int e = 0; e < ESZ; e++) s += m_s[e] * Vw_s[e * 132 + tid];
            lgs[tid] = s;
        }
        __syncthreads();

        if (tid < 32) {
            float mx = -1e30f;
            for (int v = lane; v < V1SZ; v += 32) mx = fmaxf(mx, lgs[v]);
            #pragma unroll
            for (int off = 16; off > 0; off >>= 1) mx = fmaxf(mx, __shfl_xor_sync(0xffffffffu, mx, off));
            float ssum = 0.f;
            for (int v = lane; v < V1SZ; v += 32) ssum += expf(lgs[v] - mx);
            #pragma unroll
            for (int off = 16; off > 0; off >>= 1) ssum += __shfl_xor_sync(0xffffffffu, ssum, off);
            if (lane == 0) { red[0] = mx; red[1] = ssum; }
        }
        __syncthreads();

        int tg = target[t * BSZ + b];
        float ls = lgs[tg] - red[0] - logf(red[1]);
        score += ls * act;
        act *= (tg != VSZ) ? 1.f : 0.f;
        __syncthreads();
    }
    if (tid == 0) out[b] = score;
}

// ---------------- host orchestration ----------------
extern "C" void kernel_launch(void* const* d_in, const int* in_sizes, int n_in,
                              void* d_out, int out_size) {
    const int*   inputs  = (const int*)  d_in[0];
    const int*   target  = (const int*)  d_in[1];
    const float* enc_Wih = (const float*)d_in[2];
    const float* enc_Whh = (const float*)d_in[3];
    const float* enc_bih = (const float*)d_in[4];
    const float* enc_bhh = (const float*)d_in[5];
    const float* enc_h0  = (const float*)d_in[6];
    const float* enc_c0  = (const float*)d_in[7];
    const float* dec_Wih = (const float*)d_in[8];
    const float* dec_Whh = (const float*)d_in[9];
    const float* dec_bih = (const float*)d_in[10];
    const float* dec_bhh = (const float*)d_in[11];
    const float* dec_c0  = (const float*)d_in[12];
    const float* W_w     = (const float*)d_in[13];
    const float* W_b     = (const float*)d_in[14];
    const float* V_w     = (const float*)d_in[15];
    const float* V_b     = (const float*)d_in[16];
    const float* A_w     = (const float*)d_in[17];
    float* out = (float*)d_out;

    __nv_bfloat16 *WhhPE_p, *WhhPD_p, *Awb_p, *Wwb_p, *hbf_p, *hcbf_p, *Hs_p, *Hd_p, *ubf_p;
    float *WihPE_p, *WihPD_p, *ebE_p, *ebD_p, *fc_p;
    cudaGetSymbolAddress((void**)&WhhPE_p, g_WhhPE);
    cudaGetSymbolAddress((void**)&WhhPD_p, g_WhhPD);
    cudaGetSymbolAddress((void**)&WihPE_p, g_WihPE);
    cudaGetSymbolAddress((void**)&WihPD_p, g_WihPD);
    cudaGetSymbolAddress((void**)&ebE_p, g_ebE);
    cudaGetSymbolAddress((void**)&ebD_p, g_ebD);
    cudaGetSymbolAddress((void**)&Awb_p, g_Awb);
    cudaGetSymbolAddress((void**)&Wwb_p, g_Wwb);
    cudaGetSymbolAddress((void**)&hbf_p, g_hbf);
    cudaGetSymbolAddress((void**)&hcbf_p, g_hcbf);
    cudaGetSymbolAddress((void**)&Hs_p, g_Hs);
    cudaGetSymbolAddress((void**)&Hd_p, g_Hd);
    cudaGetSymbolAddress((void**)&ubf_p, g_ubf);
    cudaGetSymbolAddress((void**)&fc_p, g_fc);

    const int ps_smem = (ESZ * 132 + ESZ + 132) * (int)sizeof(float);
    cudaFuncSetAttribute(pool_score_all_kernel, cudaFuncAttributeMaxDynamicSharedMemorySize, ps_smem);
    const int step_smem = 3 * (256 + 128) * 40 * 2;   // 92160 B
    cudaFuncSetAttribute(lstm_step_kernel, cudaFuncAttributeMaxDynamicSharedMemorySize, step_smem);

    // ---- weight prep ----
    permute_lstm_weights_kernel<<<H4SZ, 256>>>(enc_Whh, enc_bih, enc_bhh, enc_Wih,
                                               WhhPE_p, ebE_p, WihPE_p);
    permute_lstm_weights_kernel<<<H4SZ, 256>>>(dec_Whh, dec_bih, dec_bhh, dec_Wih,
                                               WhhPD_p, ebD_p, WihPD_p);
    convert_bf16_kernel<<<(HSZ * HSZ + 255) / 256, 256>>>(A_w, Awb_p, HSZ * HSZ);
    convert_bf16_kernel<<<(ESZ * 2 * HSZ + 255) / 256, 256>>>(W_w, Wwb_p, ESZ * 2 * HSZ);

    // ---- init ----
    init_hc_kernel<<<(NB * HSZ + 255) / 256, 256>>>(enc_h0, enc_c0);
    init_mask_kernel<<<(NB + 255) / 256, 256>>>(inputs);

    const dim3 step_grid(H4SZ / 128, NB / 256);   // (16, 8) = 128 CTAs

    // ---- encoder: 32 fused steps (time-major Hs) ----
    for (int t = 0; t < LLEN; t++) {
        const __nv_bfloat16* Ain = (t == 0) ? hbf_p : (Hs_p + (size_t)(t - 1) * NB * HSZ);
        lstm_step_kernel<<<step_grid, 256, step_smem>>>(
            Ain, WhhPE_p, Hs_p + (size_t)t * NB * HSZ,
            ebE_p, WihPE_p, inputs + t * BSZ, 1);
    }

    // ---- decoder init + 31 target-fed steps ----
    gather_emb_kernel<<<(NB * HSZ) / 256, 256>>>(dec_c0);
    lstm_step_kernel<<<step_grid, 256, step_smem>>>(
        hbf_p, WhhPD_p, Hd_p, ebD_p, WihPD_p, (const int*)nullptr, 0);
    for (int t = 1; t < TLEN; t++) {
        lstm_step_kernel<<<step_grid, 256, step_smem>>>(
            Hd_p + (size_t)(t - 1) * NB * HSZ, WhhPD_p, Hd_p + (size_t)t * NB * HSZ,
            ebD_p, WihPD_p, target + (t - 1) * BSZ, 2);
    }

    // ---- batched decoder tail ----
    bf16_gemm_kernel<4><<<dim3(HSZ / 128, NT_ALL / 128), 256>>>(
        Hd_p, Awb_p, (void*)ubf_p, NT_ALL, HSZ, HSZ, nullptr);
    attn_all_kernel<<<NB, 256>>>();
    bf16_gemm_kernel<2><<<dim3(ESZ / 128, NT_ALL / 128), 256>>>(
        hcbf_p, Wwb_p, (void*)fc_p, NT_ALL, ESZ, 2 * HSZ, W_b);
    pool_score_all_kernel<<<BSZ, 256, ps_smem>>>(V_w, V_b, target, out);
}

// round 7
// speedup vs baseline: 1.3489x; 1.3489x over previous
#include <cuda_runtime.h>
#include <cuda_bf16.h>
#include <math.h>
#include <stdint.h>

// ---------------- problem constants ----------------
#define VSZ   128
#define V1SZ  129
#define HSZ   512
#define H4SZ  2048
#define ESZ   128
#define NEXN  4
#define LLEN  32
#define BSZ   512
#define TLEN  32
#define NB    (NEXN * BSZ)      // 2048
#define NT_ALL (TLEN * NB)      // 65536
#define NEGV  (-1e9f)

// ---------------- device scratch (allocation-free) ----------------
__device__ __nv_bfloat16 g_Hs[(size_t)LLEN * NB * HSZ];   // 64 MB encoder hiddens, time-major
__device__ __nv_bfloat16 g_Hd[(size_t)TLEN * NB * HSZ];   // 64 MB decoder hiddens, time-major
__device__ __nv_bfloat16 g_hbf[NB * HSZ];                 // h input for t=0 steps
__device__ float g_c[NB * HSZ];
__device__ __nv_bfloat16 g_ubf[(size_t)NT_ALL * HSZ];     // 64 MB u (bf16)
__device__ __nv_bfloat16 g_hcbf[(size_t)NT_ALL * 2 * HSZ];// 128 MB [h,ctx]
__device__ float g_fc[(size_t)NT_ALL * ESZ];              // 32 MB
__device__ float g_mask[NEXN * LLEN * BSZ];
__device__ int   g_idx[NB];
// permuted / converted weights
__device__ __nv_bfloat16 g_WhhPE[H4SZ * HSZ];             // gate-interleaved enc Whh (bf16)
__device__ __nv_bfloat16 g_WhhPD[H4SZ * HSZ];
__device__ float g_WihPE[H4SZ * V1SZ];
__device__ float g_WihPD[H4SZ * V1SZ];
__device__ float g_ebE[H4SZ];
__device__ float g_ebD[H4SZ];
__device__ __nv_bfloat16 g_Awb[HSZ * HSZ];
__device__ __nv_bfloat16 g_Wwb[ESZ * 2 * HSZ];

__device__ __forceinline__ float sigmoidf_(float x) { return 1.f / (1.f + expf(-x)); }

// ---------------- ptx helpers ----------------
__device__ __forceinline__ void cp_async16(uint32_t dst, const void* src) {
    asm volatile("cp.async.cg.shared.global [%0], [%1], 16;\n" :: "r"(dst), "l"(src));
}
__device__ __forceinline__ void cp_commit() { asm volatile("cp.async.commit_group;\n"); }
template<int N> __device__ __forceinline__ void cp_wait() {
    asm volatile("cp.async.wait_group %0;\n" :: "n"(N));
}
__device__ __forceinline__ void ldm_x4(uint32_t& r0, uint32_t& r1, uint32_t& r2, uint32_t& r3,
                                       uint32_t addr) {
    asm volatile("ldmatrix.sync.aligned.m8n8.x4.shared.b16 {%0,%1,%2,%3}, [%4];"
                 : "=r"(r0), "=r"(r1), "=r"(r2), "=r"(r3) : "r"(addr));
}

// ---------------- weight prep ----------------
__global__ void convert_bf16_kernel(const float* __restrict__ src,
                                    __nv_bfloat16* __restrict__ dst, int n) {
    int i = blockIdx.x * blockDim.x + threadIdx.x;
    if (i < n) dst[i] = __float2bfloat16_rn(src[i]);
}

// gate-interleave permutation: n' = 4h+gate  <-  orig = gate*H + h
__global__ void permute_lstm_weights_kernel(
    const float* __restrict__ Whh, const float* __restrict__ bih,
    const float* __restrict__ bhh, const float* __restrict__ Wih,
    __nv_bfloat16* __restrict__ WhhP, float* __restrict__ eb, float* __restrict__ WihP) {
    int np = blockIdx.x;                  // 0..2047
    int h = np >> 2, g = np & 3;
    int orig = g * HSZ + h;
    for (int k = threadIdx.x; k < HSZ; k += 256)
        WhhP[np * HSZ + k] = __float2bfloat16_rn(Whh[(size_t)orig * HSZ + k]);
    for (int v = threadIdx.x; v < V1SZ; v += 256)
        WihP[np * V1SZ + v] = Wih[(size_t)orig * V1SZ + v];
    if (threadIdx.x == 0) eb[np] = bih[orig] + bhh[orig];
}

// ---------------- init kernels ----------------
__global__ void init_hc_kernel(const float* __restrict__ h0, const float* __restrict__ c0) {
    int idx = blockIdx.x * blockDim.x + threadIdx.x;
    if (idx < NB * HSZ) {
        int hh = idx & (HSZ - 1);
        g_hbf[idx] = __float2bfloat16_rn(h0[hh]);
        g_c[idx] = c0[hh];
    }
}

__global__ void init_mask_kernel(const int* __restrict__ inputs) {
    int r = blockIdx.x * blockDim.x + threadIdx.x;
    if (r < NB) {
        int j = r / BSZ, b = r % BSZ;
        float a = 1.f;
        int cnt = 0;
        #pragma unroll
        for (int l = 0; l < LLEN; l++) {
            g_mask[(j * LLEN + l) * BSZ + b] = (a > 0.f) ? 0.f : NEGV;
            cnt += (a > 0.f) ? 1 : 0;
            a *= (inputs[(j * LLEN + l) * BSZ + b] != VSZ) ? 1.f : 0.f;
        }
        g_idx[r] = cnt - 1;
    }
}

// ================= fused GEMM + LSTM cell =================
// CTA tile 128x128, 8 warps 4(m) x 2(n), warp tile 32x64. 3-stage cp.async.
// __launch_bounds__(256, 2): regs capped at 128 -> 2 CTAs/SM -> all 256 CTAs in ONE wave.
// gates = A @ WhhP^T (+ eb + WihP[:,tok]); LSTM pointwise update in epilogue.
// tokmode: 0 = SOS (tok=VSZ); 1 = encoder; 2 = decoder
__global__ __launch_bounds__(256, 2)
void lstm_step_kernel(const __nv_bfloat16* __restrict__ A,
                      const __nv_bfloat16* __restrict__ Bw,
                      __nv_bfloat16* __restrict__ Hout,
                      const float* __restrict__ eb, const float* __restrict__ WihP,
                      const int* __restrict__ tokp, int tokmode) {
    constexpr int BM = 128, BN = 128, BK = 32, K = HSZ;
    constexpr int AST = 40;                       // 80B row stride, conflict-free ldmatrix
    constexpr int MT = 2, NTc = 8;                // warp tile 32x64
    constexpr int STAGE = (BM + BN) * AST;        // 10240 bf16 per stage
    constexpr int NSTAGE = 3;
    constexpr int NIT = K / BK;                   // 16

    extern __shared__ __nv_bfloat16 smd[];
    const uint32_t smbase = (uint32_t)__cvta_generic_to_shared(smd);

    const int tid = threadIdx.x;
    const int warp = tid >> 5, lane = tid & 31;
    const int wm = warp >> 1;                     // 0..3
    const int wn = warp & 1;                      // 0..1
    const int m0 = blockIdx.y * BM, n0 = blockIdx.x * BN;

    float acc[MT][NTc][4];
    #pragma unroll
    for (int mt = 0; mt < MT; mt++)
        #pragma unroll
        for (int nt = 0; nt < NTc; nt++)
            #pragma unroll
            for (int q = 0; q < 4; q++) acc[mt][nt][q] = 0.f;

    auto load_stage = [&](int it) {
        const int k0 = it * BK;
        const uint32_t base = smbase + (uint32_t)(it % NSTAGE) * STAGE * 2;
        #pragma unroll
        for (int ii = 0; ii < (BM + BN) * 4 / 256; ii++) {
            int c = tid + ii * 256;
            bool isB = c >= BM * 4;
            int cc = isB ? c - BM * 4 : c;
            int row = cc >> 2, part = cc & 3;
            const __nv_bfloat16* src = isB
                ? (Bw + (size_t)(n0 + row) * K + k0 + part * 8)
                : (A  + (size_t)(m0 + row) * K + k0 + part * 8);
            uint32_t dst = base + (uint32_t)(((isB ? BM + row : row) * AST + part * 8) * 2);
            cp_async16(dst, src);
        }
        cp_commit();
    };

    load_stage(0);
    load_stage(1);

    for (int it = 0; it < NIT; it++) {
        cp_wait<1>();
        __syncthreads();
        if (it + 2 < NIT) load_stage(it + 2);

        const uint32_t aBase = smbase + (uint32_t)(it % NSTAGE) * STAGE * 2;
        const uint32_t bBase = aBase + BM * AST * 2;

        #pragma unroll
        for (int kk = 0; kk < 2; kk++) {
            uint32_t a[MT][4];
            #pragma unroll
            for (int mt = 0; mt < MT; mt++) {
                int row = wm * 32 + mt * 16 + (lane & 15);
                int col = kk * 16 + (lane >> 4) * 8;
                ldm_x4(a[mt][0], a[mt][1], a[mt][2], a[mt][3],
                       aBase + (uint32_t)((row * AST + col) * 2));
            }
            uint32_t b[NTc][2];
            #pragma unroll
            for (int ntp = 0; ntp < NTc / 2; ntp++) {
                int row = wn * 64 + ntp * 16 + ((lane >> 4) << 3) + (lane & 7);
                int col = kk * 16 + ((lane >> 3) & 1) * 8;
                ldm_x4(b[2 * ntp][0], b[2 * ntp][1], b[2 * ntp + 1][0], b[2 * ntp + 1][1],
                       bBase + (uint32_t)((row * AST + col) * 2));
            }
            #pragma unroll
            for (int mt = 0; mt < MT; mt++)
                #pragma unroll
                for (int nt = 0; nt < NTc; nt++) {
                    asm volatile(
                        "mma.sync.aligned.m16n8k16.row.col.f32.bf16.bf16.f32 "
                        "{%0,%1,%2,%3}, {%4,%5,%6,%7}, {%8,%9}, {%0,%1,%2,%3};"
                        : "+f"(acc[mt][nt][0]), "+f"(acc[mt][nt][1]),
                          "+f"(acc[mt][nt][2]), "+f"(acc[mt][nt][3])
                        : "r"(a[mt][0]), "r"(a[mt][1]), "r"(a[mt][2]), "r"(a[mt][3]),
                          "r"(b[nt][0]), "r"(b[nt][1]));
                }
        }
        __syncthreads();
    }

    // -------- fused LSTM epilogue --------
    const unsigned FULL = 0xffffffffu;
    #pragma unroll
    for (int mt = 0; mt < MT; mt++) {
        int r_lo = m0 + wm * 32 + mt * 16 + (lane >> 2);
        int r_hi = r_lo + 8;
        int tok_lo = VSZ, tok_hi = VSZ;
        if (tokmode == 1) {
            tok_lo = tokp[(r_lo / BSZ) * (LLEN * BSZ) + (r_lo % BSZ)];
            tok_hi = tokp[(r_hi / BSZ) * (LLEN * BSZ) + (r_hi % BSZ)];
        } else if (tokmode == 2) {
            tok_lo = tokp[r_lo % BSZ];
            tok_hi = tokp[r_hi % BSZ];
        }
        #pragma unroll
        for (int nt = 0; nt < NTc; nt++) {
            int c0 = n0 + wn * 64 + nt * 8 + 2 * (lane & 3);
            float e0 = eb[c0], e1 = eb[c0 + 1];
            float v00 = acc[mt][nt][0] + e0 + WihP[(size_t)c0 * V1SZ + tok_lo];
            float v01 = acc[mt][nt][1] + e1 + WihP[(size_t)(c0 + 1) * V1SZ + tok_lo];
            float v10 = acc[mt][nt][2] + e0 + WihP[(size_t)c0 * V1SZ + tok_hi];
            float v11 = acc[mt][nt][3] + e1 + WihP[(size_t)(c0 + 1) * V1SZ + tok_hi];
            // lane-pair exchange: even q holds (i,f), odd q holds (g,o)
            float p00 = __shfl_xor_sync(FULL, v00, 1);
            float p01 = __shfl_xor_sync(FULL, v01, 1);
            float p10 = __shfl_xor_sync(FULL, v10, 1);
            float p11 = __shfl_xor_sync(FULL, v11, 1);
            if ((lane & 1) == 0) {
                int h = c0 >> 2;
                {
                    float cold = g_c[(size_t)r_lo * HSZ + h];
                    float c2 = sigmoidf_(v01) * cold + sigmoidf_(v00) * tanhf(p00);
                    float h2 = sigmoidf_(p01) * tanhf(c2);
                    g_c[(size_t)r_lo * HSZ + h] = c2;
                    Hout[(size_t)r_lo * HSZ + h] = __float2bfloat16_rn(h2);
                }
                {
                    float cold = g_c[(size_t)r_hi * HSZ + h];
                    float c2 = sigmoidf_(v11) * cold + sigmoidf_(v10) * tanhf(p10);
                    float h2 = sigmoidf_(p11) * tanhf(c2);
                    g_c[(size_t)r_hi * HSZ + h] = c2;
                    Hout[(size_t)r_hi * HSZ + h] = __float2bfloat16_rn(h2);
                }
            }
        }
    }
}

// ================= generic bf16 GEMM (tail, batched) =================
// MODE 0: f32 store; MODE 2: tanh(+b1) f32 store; MODE 4: bf16 store
template<int MODE>
__global__ __launch_bounds__(256)
void bf16_gemm_kernel(const __nv_bfloat16* __restrict__ A, const __nv_bfloat16* __restrict__ Bw,
                      void* __restrict__ Cv, int M, int N, int K,
                      const float* __restrict__ b1) {
    constexpr int BM = 128, BN = 128, BK = 32;
    constexpr int AST = 40;
    constexpr int MT = 2, NTc = 8;
    constexpr int STAGE = (BM + BN) * AST;

    __shared__ __nv_bfloat16 sm[2 * STAGE];
    const uint32_t smbase = (uint32_t)__cvta_generic_to_shared(sm);

    const int tid = threadIdx.x;
    const int warp = tid >> 5, lane = tid & 31;
    const int wm = warp >> 1;
    const int wn = warp & 1;
    const int m0 = blockIdx.y * BM, n0 = blockIdx.x * BN;
    const int NIT = K / BK;

    float acc[MT][NTc][4];
    #pragma unroll
    for (int mt = 0; mt < MT; mt++)
        #pragma unroll
        for (int nt = 0; nt < NTc; nt++)
            #pragma unroll
            for (int q = 0; q < 4; q++) acc[mt][nt][q] = 0.f;

    auto load_stage = [&](int it, int buf) {
        const int k0 = it * BK;
        const uint32_t base = smbase + (uint32_t)buf * STAGE * 2;
        #pragma unroll
        for (int c = tid; c < (BM + BN) * 4; c += 256) {
            bool isB = c >= BM * 4;
            int cc = isB ? c - BM * 4 : c;
            int row = cc >> 2, part = cc & 3;
            const __nv_bfloat16* src = isB
                ? (Bw + (size_t)(n0 + row) * K + k0 + part * 8)
                : (A  + (size_t)(m0 + row) * K + k0 + part * 8);
            uint32_t dst = base + (uint32_t)(((isB ? BM + row : row) * AST + part * 8) * 2);
            cp_async16(dst, src);
        }
    };

    load_stage(0, 0);
    cp_commit();

    for (int it = 0; it < NIT; it++) {
        if (it + 1 < NIT) { load_stage(it + 1, (it + 1) & 1); cp_commit(); cp_wait<1>(); }
        else              { cp_wait<0>(); }
        __syncthreads();

        const uint32_t aBase = smbase + (uint32_t)(it & 1) * STAGE * 2;
        const uint32_t bBase = aBase + BM * AST * 2;

        #pragma unroll
        for (int kk = 0; kk < 2; kk++) {
            uint32_t a[MT][4];
            #pragma unroll
            for (int mt = 0; mt < MT; mt++) {
                int row = wm * 32 + mt * 16 + (lane & 15);
                int col = kk * 16 + (lane >> 4) * 8;
                ldm_x4(a[mt][0], a[mt][1], a[mt][2], a[mt][3],
                       aBase + (uint32_t)((row * AST + col) * 2));
            }
            uint32_t b[NTc][2];
            #pragma unroll
            for (int ntp = 0; ntp < NTc / 2; ntp++) {
                int row = wn * 64 + ntp * 16 + ((lane >> 4) << 3) + (lane & 7);
                int col = kk * 16 + ((lane >> 3) & 1) * 8;
                ldm_x4(b[2 * ntp][0], b[2 * ntp][1], b[2 * ntp + 1][0], b[2 * ntp + 1][1],
                       bBase + (uint32_t)((row * AST + col) * 2));
            }
            #pragma unroll
            for (int mt = 0; mt < MT; mt++)
                #pragma unroll
                for (int nt = 0; nt < NTc; nt++) {
                    asm volatile(
                        "mma.sync.aligned.m16n8k16.row.col.f32.bf16.bf16.f32 "
                        "{%0,%1,%2,%3}, {%4,%5,%6,%7}, {%8,%9}, {%0,%1,%2,%3};"
                        : "+f"(acc[mt][nt][0]), "+f"(acc[mt][nt][1]),
                          "+f"(acc[mt][nt][2]), "+f"(acc[mt][nt][3])
                        : "r"(a[mt][0]), "r"(a[mt][1]), "r"(a[mt][2]), "r"(a[mt][3]),
                          "r"(b[nt][0]), "r"(b[nt][1]));
                }
        }
        __syncthreads();
    }

    float* Cf = (float*)Cv;
    __nv_bfloat16* Cb = (__nv_bfloat16*)Cv;
    #pragma unroll
    for (int mt = 0; mt < MT; mt++) {
        int r_lo = m0 + wm * 32 + mt * 16 + (lane >> 2);
        int r_hi = r_lo + 8;
        #pragma unroll
        for (int nt = 0; nt < NTc; nt++) {
            int c0 = n0 + wn * 64 + nt * 8 + 2 * (lane & 3);
            float v00 = acc[mt][nt][0], v01 = acc[mt][nt][1];
            float v10 = acc[mt][nt][2], v11 = acc[mt][nt][3];
            if (MODE == 2) {
                float bb0 = b1[c0], bb1 = b1[c0 + 1];
                v00 = tanhf(v00 + bb0); v01 = tanhf(v01 + bb1);
                v10 = tanhf(v10 + bb0); v11 = tanhf(v11 + bb1);
            }
            if (MODE == 4) {
                __nv_bfloat162 lo = __floats2bfloat162_rn(v00, v01);
                __nv_bfloat162 hi = __floats2bfloat162_rn(v10, v11);
                *(__nv_bfloat162*)&Cb[(size_t)r_lo * N + c0] = lo;
                *(__nv_bfloat162*)&Cb[(size_t)r_hi * N + c0] = hi;
            } else {
                Cf[(size_t)r_lo * N + c0] = v00;
                Cf[(size_t)r_lo * N + c0 + 1] = v01;
                Cf[(size_t)r_hi * N + c0] = v10;
                Cf[(size_t)r_hi * N + c0 + 1] = v11;
            }
        }
    }
}

// ---------------- gather final-hidden embedding, set decoder c0 ----------------
__global__ void gather_emb_kernel(const float* __restrict__ dec_c0) {
    int idx = blockIdx.x * blockDim.x + threadIdx.x;
    if (idx >= NB * HSZ) return;
    int r = idx >> 9;
    int hh = idx & (HSZ - 1);
    int li = g_idx[r];
    g_hbf[idx] = g_Hs[((size_t)li * NB + r) * HSZ + hh];
    g_c[idx] = dec_c0[hh];
}

// ---------------- batched attention over all 32 timesteps ----------------
__global__ __launch_bounds__(256) void attn_all_kernel() {
    __shared__ __nv_bfloat16 hs_s[LLEN * HSZ];   // 32 KB
    __shared__ float u_s[HSZ];
    __shared__ float sc[LLEN];
    __shared__ float mask_s[LLEN];

    const int r = blockIdx.x;
    const int j = r / BSZ;
    const int tid = threadIdx.x;
    const int warp = tid >> 5, lane = tid & 31;

    #pragma unroll
    for (int idx = tid; idx < LLEN * HSZ / 8; idx += 256) {
        int l = idx >> 6;
        int c8 = (idx & 63) * 8;
        uint4 v = *(const uint4*)&g_Hs[((size_t)l * NB + r) * HSZ + c8];
        *(uint4*)&hs_s[l * HSZ + c8] = v;
    }
    if (tid < LLEN) mask_s[tid] = g_mask[(j * LLEN + tid) * BSZ + (r % BSZ)];
    __syncthreads();

    for (int t = 0; t < TLEN; t++) {
        const size_t row = (size_t)t * NB + r;
        for (int k = tid; k < HSZ; k += 256)
            u_s[k] = __bfloat162float(g_ubf[row * HSZ + k]);
        __syncthreads();

        for (int l = warp; l < LLEN; l += 8) {
            float s = 0.f;
            for (int k = lane; k < HSZ; k += 32)
                s += __bfloat162float(hs_s[l * HSZ + k]) * u_s[k];
            #pragma unroll
            for (int off = 16; off > 0; off >>= 1) s += __shfl_down_sync(0xffffffffu, s, off);
            if (lane == 0) sc[l] = s + mask_s[l];
        }
        __syncthreads();

        if (warp == 0) {
            float v = sc[lane];
            float mx = v;
            #pragma unroll
            for (int off = 16; off > 0; off >>= 1) mx = fmaxf(mx, __shfl_xor_sync(0xffffffffu, mx, off));
            float e = expf(v - mx);
            float ssum = e;
            #pragma unroll
            for (int off = 16; off > 0; off >>= 1) ssum += __shfl_xor_sync(0xffffffffu, ssum, off);
            sc[lane] = e / ssum;
        }
        __syncthreads();

        __nv_bfloat16* hc = g_hcbf + row * (2 * HSZ);
        #pragma unroll
        for (int kq = 0; kq < 2; kq++) {
            int k = tid + kq * 256;
            float cx = 0.f;
            #pragma unroll
            for (int l = 0; l < LLEN; l++) cx += sc[l] * __bfloat162float(hs_s[l * HSZ + k]);
            hc[HSZ + k] = __float2bfloat16_rn(cx);
        }
        if (tid < 64) {
            uint4 v = *(const uint4*)&g_Hd[row * HSZ + tid * 8];
            *(uint4*)&hc[tid * 8] = v;
        }
        __syncthreads();
    }
}

// ---------------- pool + logits + log-softmax + score over all t ----------------
__global__ __launch_bounds__(256) void pool_score_all_kernel(
    const float* __restrict__ Vw, const float* __restrict__ Vb,
    const int* __restrict__ target, float* __restrict__ out) {
    extern __shared__ float dsm[];
    float* Vw_s = dsm;                 // [128][132] e-major, padded
    float* m_s  = dsm + ESZ * 132;
    float* lgs  = m_s + ESZ;
    __shared__ float red[2];

    const int b = blockIdx.x;
    const int tid = threadIdx.x;
    const int lane = tid & 31;

    for (int idx = tid; idx < V1SZ * ESZ; idx += 256) {
        int v = idx >> 7, e = idx & 127;
        Vw_s[e * 132 + v] = Vw[(size_t)v * ESZ + e];
    }
    __syncthreads();

    float score = 0.f, act = 1.f;
    for (int t = 0; t < TLEN; t++) {
        if (tid < ESZ) {
            const size_t base = ((size_t)t * NB + b) * ESZ + tid;
            float m = g_fc[base];
            #pragma unroll
            for (int jj = 1; jj < NEXN; jj++)
                m = fmaxf(m, g_fc[base + (size_t)jj * BSZ * ESZ]);
            m_s[tid] = m;
        }
        __syncthreads();

        if (tid < V1SZ) {
            float s = Vb[tid];
            #pragma unroll 8
            for (int e = 0; e < ESZ; e++) s += m_s[e] * Vw_s[e * 132 + tid];
            lgs[tid] = s;
        }
        __syncthreads();

        if (tid < 32) {
            float mx = -1e30f;
            for (int v = lane; v < V1SZ; v += 32) mx = fmaxf(mx, lgs[v]);
            #pragma unroll
            for (int off = 16; off > 0; off >>= 1) mx = fmaxf(mx, __shfl_xor_sync(0xffffffffu, mx, off));
            float ssum = 0.f;
            for (int v = lane; v < V1SZ; v += 32) ssum += expf(lgs[v] - mx);
            #pragma unroll
            for (int off = 16; off > 0; off >>= 1) ssum += __shfl_xor_sync(0xffffffffu, ssum, off);
            if (lane == 0) { red[0] = mx; red[1] = ssum; }
        }
        __syncthreads();

        int tg = target[t * BSZ + b];
        float ls = lgs[tg] - red[0] - logf(red[1]);
        score += ls * act;
        act *= (tg != VSZ) ? 1.f : 0.f;
        __syncthreads();
    }
    if (tid == 0) out[b] = score;
}

// ---------------- host orchestration ----------------
extern "C" void kernel_launch(void* const* d_in, const int* in_sizes, int n_in,
                              void* d_out, int out_size) {
    const int*   inputs  = (const int*)  d_in[0];
    const int*   target  = (const int*)  d_in[1];
    const float* enc_Wih = (const float*)d_in[2];
    const float* enc_Whh = (const float*)d_in[3];
    const float* enc_bih = (const float*)d_in[4];
    const float* enc_bhh = (const float*)d_in[5];
    const float* enc_h0  = (const float*)d_in[6];
    const float* enc_c0  = (const float*)d_in[7];
    const float* dec_Wih = (const float*)d_in[8];
    const float* dec_Whh = (const float*)d_in[9];
    const float* dec_bih = (const float*)d_in[10];
    const float* dec_bhh = (const float*)d_in[11];
    const float* dec_c0  = (const float*)d_in[12];
    const float* W_w     = (const float*)d_in[13];
    const float* W_b     = (const float*)d_in[14];
    const float* V_w     = (const float*)d_in[15];
    const float* V_b     = (const float*)d_in[16];
    const float* A_w     = (const float*)d_in[17];
    float* out = (float*)d_out;

    __nv_bfloat16 *WhhPE_p, *WhhPD_p, *Awb_p, *Wwb_p, *hbf_p, *hcbf_p, *Hs_p, *Hd_p, *ubf_p;
    float *WihPE_p, *WihPD_p, *ebE_p, *ebD_p, *fc_p;
    cudaGetSymbolAddress((void**)&WhhPE_p, g_WhhPE);
    cudaGetSymbolAddress((void**)&WhhPD_p, g_WhhPD);
    cudaGetSymbolAddress((void**)&WihPE_p, g_WihPE);
    cudaGetSymbolAddress((void**)&WihPD_p, g_WihPD);
    cudaGetSymbolAddress((void**)&ebE_p, g_ebE);
    cudaGetSymbolAddress((void**)&ebD_p, g_ebD);
    cudaGetSymbolAddress((void**)&Awb_p, g_Awb);
    cudaGetSymbolAddress((void**)&Wwb_p, g_Wwb);
    cudaGetSymbolAddress((void**)&hbf_p, g_hbf);
    cudaGetSymbolAddress((void**)&hcbf_p, g_hcbf);
    cudaGetSymbolAddress((void**)&Hs_p, g_Hs);
    cudaGetSymbolAddress((void**)&Hd_p, g_Hd);
    cudaGetSymbolAddress((void**)&ubf_p, g_ubf);
    cudaGetSymbolAddress((void**)&fc_p, g_fc);

    const int ps_smem = (ESZ * 132 + ESZ + 132) * (int)sizeof(float);
    cudaFuncSetAttribute(pool_score_all_kernel, cudaFuncAttributeMaxDynamicSharedMemorySize, ps_smem);
    const int step_smem = 3 * (128 + 128) * 40 * 2;   // 61440 B per CTA (3 stages)
    cudaFuncSetAttribute(lstm_step_kernel, cudaFuncAttributeMaxDynamicSharedMemorySize, step_smem);

    // ---- weight prep ----
    permute_lstm_weights_kernel<<<H4SZ, 256>>>(enc_Whh, enc_bih, enc_bhh, enc_Wih,
                                               WhhPE_p, ebE_p, WihPE_p);
    permute_lstm_weights_kernel<<<H4SZ, 256>>>(dec_Whh, dec_bih, dec_bhh, dec_Wih,
                                               WhhPD_p, ebD_p, WihPD_p);
    convert_bf16_kernel<<<(HSZ * HSZ + 255) / 256, 256>>>(A_w, Awb_p, HSZ * HSZ);
    convert_bf16_kernel<<<(ESZ * 2 * HSZ + 255) / 256, 256>>>(W_w, Wwb_p, ESZ * 2 * HSZ);

    // ---- init ----
    init_hc_kernel<<<(NB * HSZ + 255) / 256, 256>>>(enc_h0, enc_c0);
    init_mask_kernel<<<(NB + 255) / 256, 256>>>(inputs);

    const dim3 step_grid(H4SZ / 128, NB / 128);   // (16, 16) = 256 CTAs, 2/SM resident

    // ---- encoder: 32 fused steps (time-major Hs) ----
    for (int t = 0; t < LLEN; t++) {
        const __nv_bfloat16* Ain = (t == 0) ? hbf_p : (Hs_p + (size_t)(t - 1) * NB * HSZ);
        lstm_step_kernel<<<step_grid, 256, step_smem>>>(
            Ain, WhhPE_p, Hs_p + (size_t)t * NB * HSZ,
            ebE_p, WihPE_p, inputs + t * BSZ, 1);
    }

    // ---- decoder init + 31 target-fed steps ----
    gather_emb_kernel<<<(NB * HSZ) / 256, 256>>>(dec_c0);
    lstm_step_kernel<<<step_grid, 256, step_smem>>>(
        hbf_p, WhhPD_p, Hd_p, ebD_p, WihPD_p, (const int*)nullptr, 0);
    for (int t = 1; t < TLEN; t++) {
        lstm_step_kernel<<<step_grid, 256, step_smem>>>(
            Hd_p + (size_t)(t - 1) * NB * HSZ, WhhPD_p, Hd_p + (size_t)t * NB * HSZ,
            ebD_p, WihPD_p, target + (t - 1) * BSZ, 2);
    }

    // ---- batched decoder tail ----
    bf16_gemm_kernel<4><<<dim3(HSZ / 128, NT_ALL / 128), 256>>>(
        Hd_p, Awb_p, (void*)ubf_p, NT_ALL, HSZ, HSZ, nullptr);
    attn_all_kernel<<<NB, 256>>>();
    bf16_gemm_kernel<2><<<dim3(ESZ / 128, NT_ALL / 128), 256>>>(
        hcbf_p, Wwb_p, (void*)fc_p, NT_ALL, ESZ, 2 * HSZ, W_b);
    pool_score_all_kernel<<<BSZ, 256, ps_smem>>>(V_w, V_b, target, out);
}

// round 8
// speedup vs baseline: 1.3768x; 1.0207x over previous
#include <cuda_runtime.h>
#include <cuda_bf16.h>
#include <math.h>
#include <stdint.h>

// ---------------- problem constants ----------------
#define VSZ   128
#define V1SZ  129
#define HSZ   512
#define H4SZ  2048
#define ESZ   128
#define NEXN  4
#define LLEN  32
#define BSZ   512
#define TLEN  32
#define NB    (NEXN * BSZ)      // 2048
#define NT_ALL (TLEN * NB)      // 65536
#define NEGV  (-1e9f)
#define NBH   ((size_t)NB * HSZ)

// ---------------- device scratch (allocation-free) ----------------
__device__ __nv_bfloat16 g_Hs[(size_t)LLEN * NB * HSZ];   // encoder hiddens, time-major
__device__ __nv_bfloat16 g_Hd[(size_t)TLEN * NB * HSZ];   // decoder hiddens, time-major
__device__ __nv_bfloat16 g_hbf[NB * HSZ];                 // h input for t=0
__device__ __nv_bfloat16 g_ubf[(size_t)NT_ALL * HSZ];
__device__ __nv_bfloat16 g_hcbf[(size_t)NT_ALL * 2 * HSZ];
__device__ float g_fc[(size_t)NT_ALL * ESZ];
__device__ float g_mask[NEXN * LLEN * BSZ];
__device__ int   g_idx[NB];
__device__ unsigned int g_bar;                            // grid barrier counter
// permuted / converted weights
__device__ __nv_bfloat16 g_WhhPE[H4SZ * HSZ];
__device__ __nv_bfloat16 g_WhhPD[H4SZ * HSZ];
__device__ float g_WihPE[H4SZ * V1SZ];
__device__ float g_WihPD[H4SZ * V1SZ];
__device__ float g_ebE[H4SZ];
__device__ float g_ebD[H4SZ];
__device__ __nv_bfloat16 g_Awb[HSZ * HSZ];
__device__ __nv_bfloat16 g_Wwb[ESZ * 2 * HSZ];

__device__ __forceinline__ float sigmoidf_(float x) { return 1.f / (1.f + expf(-x)); }

// ---------------- ptx helpers ----------------
__device__ __forceinline__ void cp_async16(uint32_t dst, const void* src) {
    asm volatile("cp.async.cg.shared.global [%0], [%1], 16;\n" :: "r"(dst), "l"(src));
}
__device__ __forceinline__ void cp_commit() { asm volatile("cp.async.commit_group;\n"); }
template<int N> __device__ __forceinline__ void cp_wait() {
    asm volatile("cp.async.wait_group %0;\n" :: "n"(N));
}
__device__ __forceinline__ void ldm_x4(uint32_t& r0, uint32_t& r1, uint32_t& r2, uint32_t& r3,
                                       uint32_t addr) {
    asm volatile("ldmatrix.sync.aligned.m8n8.x4.shared.b16 {%0,%1,%2,%3}, [%4];"
                 : "=r"(r0), "=r"(r1), "=r"(r2), "=r"(r3) : "r"(addr));
}

// ---------------- weight prep ----------------
__global__ void convert_bf16_kernel(const float* __restrict__ src,
                                    __nv_bfloat16* __restrict__ dst, int n) {
    int i = blockIdx.x * blockDim.x + threadIdx.x;
    if (i < n) dst[i] = __float2bfloat16_rn(src[i]);
}

__global__ void permute_lstm_weights_kernel(
    const float* __restrict__ Whh, const float* __restrict__ bih,
    const float* __restrict__ bhh, const float* __restrict__ Wih,
    __nv_bfloat16* __restrict__ WhhP, float* __restrict__ eb, float* __restrict__ WihP) {
    int np = blockIdx.x;                  // n' = 4h+gate
    int h = np >> 2, g = np & 3;
    int orig = g * HSZ + h;
    for (int k = threadIdx.x; k < HSZ; k += 256)
        WhhP[np * HSZ + k] = __float2bfloat16_rn(Whh[(size_t)orig * HSZ + k]);
    for (int v = threadIdx.x; v < V1SZ; v += 256)
        WihP[np * V1SZ + v] = Wih[(size_t)orig * V1SZ + v];
    if (threadIdx.x == 0) eb[np] = bih[orig] + bhh[orig];
}

// ---------------- init kernels ----------------
__global__ void init_h_kernel(const float* __restrict__ h0) {
    int idx = blockIdx.x * blockDim.x + threadIdx.x;
    if (idx < NB * HSZ) g_hbf[idx] = __float2bfloat16_rn(h0[idx & (HSZ - 1)]);
}

__global__ void init_mask_kernel(const int* __restrict__ inputs) {
    int r = blockIdx.x * blockDim.x + threadIdx.x;
    if (r == 0) g_bar = 0u;               // reset grid barrier every invocation/replay
    if (r < NB) {
        int j = r / BSZ, b = r % BSZ;
        float a = 1.f;
        int cnt = 0;
        #pragma unroll
        for (int l = 0; l < LLEN; l++) {
            g_mask[(j * LLEN + l) * BSZ + b] = (a > 0.f) ? 0.f : NEGV;
            cnt += (a > 0.f) ? 1 : 0;
            a *= (inputs[(j * LLEN + l) * BSZ + b] != VSZ) ? 1.f : 0.f;
        }
        g_idx[r] = cnt - 1;
    }
}

// ================= persistent fused LSTM chain =================
// 256 CTAs (16 n-tiles x 16 m-tiles), 2 CTAs/SM, all resident -> software grid barrier.
// Each CTA: 128x128 gate tile; c tile (128 rows x 32 h) lives in SMEM for all 64 steps.
// Steps 0..31 encoder, 32 decoder-init (gather emb, reset c), 33..63 decoder.
__global__ __launch_bounds__(256, 2)
void chain_kernel(const int* __restrict__ inputs, const int* __restrict__ target,
                  const float* __restrict__ enc_c0, const float* __restrict__ dec_c0) {
    constexpr int BM = 128, BN = 128, BK = 32, K = HSZ;
    constexpr int AST = 40;
    constexpr int MT = 2, NTc = 8;
    constexpr int STAGE = (BM + BN) * AST;        // bf16 elems per stage
    constexpr int NSTAGE = 3;
    constexpr int NIT = K / BK;                   // 16

    extern __shared__ __nv_bfloat16 smd[];
    float* c_s = (float*)(smd + NSTAGE * STAGE);  // [32 h][128 rows]
    const uint32_t smbase = (uint32_t)__cvta_generic_to_shared(smd);

    const int tid = threadIdx.x;
    const int warp = tid >> 5, lane = tid & 31;
    const int wm = warp >> 1;
    const int wn = warp & 1;
    const int m0 = blockIdx.y * BM, n0 = blockIdx.x * BN;
    const unsigned FULL = 0xffffffffu;

    // init c tile from enc_c0 (broadcast over rows)
    for (int i = tid; i < 32 * 128; i += 256)
        c_s[i] = enc_c0[blockIdx.x * 32 + (i >> 7)];
    __syncthreads();

    for (int t = 0; t < LLEN + TLEN; t++) {
        const bool enc = t < LLEN;
        const __nv_bfloat16* Bw = enc ? g_WhhPE : g_WhhPD;
        const float* eb = enc ? g_ebE : g_ebD;
        const float* WihP = enc ? g_WihPE : g_WihPD;
        const __nv_bfloat16* A;
        int gather = 0;
        if (t == 0)            A = g_hbf;
        else if (t < LLEN)     A = g_Hs + (size_t)(t - 1) * NBH;
        else if (t == LLEN)  { A = g_Hs; gather = 1; }
        else                   A = g_Hd + (size_t)(t - LLEN - 1) * NBH;
        __nv_bfloat16* Hout = enc ? (g_Hs + (size_t)t * NBH)
                                  : (g_Hd + (size_t)(t - LLEN) * NBH);
        int tokmode; const int* tokp = nullptr;
        if (t < LLEN)      { tokmode = 1; tokp = inputs + t * BSZ; }
        else if (t == LLEN)  tokmode = 0;
        else               { tokmode = 2; tokp = target + (t - LLEN - 1) * BSZ; }

        if (t == LLEN) {      // decoder init: reset c to dec_c0
            for (int i = tid; i < 32 * 128; i += 256)
                c_s[i] = dec_c0[blockIdx.x * 32 + (i >> 7)];
            __syncthreads();
        }

        float acc[MT][NTc][4];
        #pragma unroll
        for (int mt = 0; mt < MT; mt++)
            #pragma unroll
            for (int nt = 0; nt < NTc; nt++)
                #pragma unroll
                for (int q = 0; q < 4; q++) acc[mt][nt][q] = 0.f;

        auto load_stage = [&](int it) {
            const int k0 = it * BK;
            const uint32_t base = smbase + (uint32_t)(it % NSTAGE) * STAGE * 2;
            #pragma unroll
            for (int ii = 0; ii < (BM + BN) * 4 / 256; ii++) {
                int c = tid + ii * 256;
                bool isB = c >= BM * 4;
                int cc = isB ? c - BM * 4 : c;
                int row = cc >> 2, part = cc & 3;
                const __nv_bfloat16* src;
                if (isB) {
                    src = Bw + (size_t)(n0 + row) * K + k0 + part * 8;
                } else if (gather) {
                    int rg = m0 + row;
                    src = g_Hs + ((size_t)g_idx[rg] * NB + rg) * HSZ + k0 + part * 8;
                } else {
                    src = A + (size_t)(m0 + row) * K + k0 + part * 8;
                }
                uint32_t dst = base + (uint32_t)(((isB ? BM + row : row) * AST + part * 8) * 2);
                cp_async16(dst, src);
            }
            cp_commit();
        };

        load_stage(0);
        load_stage(1);

        for (int it = 0; it < NIT; it++) {
            if (it == NIT - 1) cp_wait<0>(); else cp_wait<1>();
            __syncthreads();
            if (it + 2 < NIT) load_stage(it + 2);

            const uint32_t aBase = smbase + (uint32_t)(it % NSTAGE) * STAGE * 2;
            const uint32_t bBase = aBase + BM * AST * 2;

            #pragma unroll
            for (int kk = 0; kk < 2; kk++) {
                uint32_t a[MT][4];
                #pragma unroll
                for (int mt = 0; mt < MT; mt++) {
                    int row = wm * 32 + mt * 16 + (lane & 15);
                    int col = kk * 16 + (lane >> 4) * 8;
                    ldm_x4(a[mt][0], a[mt][1], a[mt][2], a[mt][3],
                           aBase + (uint32_t)((row * AST + col) * 2));
                }
                uint32_t b[NTc][2];
                #pragma unroll
                for (int ntp = 0; ntp < NTc / 2; ntp++) {
                    int row = wn * 64 + ntp * 16 + ((lane >> 4) << 3) + (lane & 7);
                    int col = kk * 16 + ((lane >> 3) & 1) * 8;
                    ldm_x4(b[2 * ntp][0], b[2 * ntp][1], b[2 * ntp + 1][0], b[2 * ntp + 1][1],
                           bBase + (uint32_t)((row * AST + col) * 2));
                }
                #pragma unroll
                for (int mt = 0; mt < MT; mt++)
                    #pragma unroll
                    for (int nt = 0; nt < NTc; nt++) {
                        asm volatile(
                            "mma.sync.aligned.m16n8k16.row.col.f32.bf16.bf16.f32 "
                            "{%0,%1,%2,%3}, {%4,%5,%6,%7}, {%8,%9}, {%0,%1,%2,%3};"
                            : "+f"(acc[mt][nt][0]), "+f"(acc[mt][nt][1]),
                              "+f"(acc[mt][nt][2]), "+f"(acc[mt][nt][3])
                            : "r"(a[mt][0]), "r"(a[mt][1]), "r"(a[mt][2]), "r"(a[mt][3]),
                              "r"(b[nt][0]), "r"(b[nt][1]));
                    }
            }
            __syncthreads();
        }

        // -------- fused LSTM epilogue (c in SMEM) --------
        #pragma unroll
        for (int mt = 0; mt < MT; mt++) {
            int rl_lo = wm * 32 + mt * 16 + (lane >> 2);      // local rows
            int rl_hi = rl_lo + 8;
            int r_lo = m0 + rl_lo, r_hi = m0 + rl_hi;
            int tok_lo = VSZ, tok_hi = VSZ;
            if (tokmode == 1) {
                tok_lo = tokp[(r_lo / BSZ) * (LLEN * BSZ) + (r_lo % BSZ)];
                tok_hi = tokp[(r_hi / BSZ) * (LLEN * BSZ) + (r_hi % BSZ)];
            } else if (tokmode == 2) {
                tok_lo = tokp[r_lo % BSZ];
                tok_hi = tokp[r_hi % BSZ];
            }
            #pragma unroll
            for (int nt = 0; nt < NTc; nt++) {
                int c0 = n0 + wn * 64 + nt * 8 + 2 * (lane & 3);
                float e0 = eb[c0], e1 = eb[c0 + 1];
                float v00 = acc[mt][nt][0] + e0 + WihP[(size_t)c0 * V1SZ + tok_lo];
                float v01 = acc[mt][nt][1] + e1 + WihP[(size_t)(c0 + 1) * V1SZ + tok_lo];
                float v10 = acc[mt][nt][2] + e0 + WihP[(size_t)c0 * V1SZ + tok_hi];
                float v11 = acc[mt][nt][3] + e1 + WihP[(size_t)(c0 + 1) * V1SZ + tok_hi];
                float p00 = __shfl_xor_sync(FULL, v00, 1);
                float p01 = __shfl_xor_sync(FULL, v01, 1);
                float p10 = __shfl_xor_sync(FULL, v10, 1);
                float p11 = __shfl_xor_sync(FULL, v11, 1);
                if ((lane & 1) == 0) {
                    int hl = wn * 16 + nt * 2 + ((lane & 3) >> 1);  // local h
                    int hg = blockIdx.x * 32 + hl;                  // global h
                    {
                        float cold = c_s[hl * 128 + rl_lo];
                        float c2 = sigmoidf_(v01) * cold + sigmoidf_(v00) * tanhf(p00);
                        float h2 = sigmoidf_(p01) * tanhf(c2);
                        c_s[hl * 128 + rl_lo] = c2;
                        Hout[(size_t)r_lo * HSZ + hg] = __float2bfloat16_rn(h2);
                    }
                    {
                        float cold = c_s[hl * 128 + rl_hi];
                        float c2 = sigmoidf_(v11) * cold + sigmoidf_(v10) * tanhf(p10);
                        float h2 = sigmoidf_(p11) * tanhf(c2);
                        c_s[hl * 128 + rl_hi] = c2;
                        Hout[(size_t)r_hi * HSZ + hg] = __float2bfloat16_rn(h2);
                    }
                }
            }
        }

        // -------- grid barrier --------
        __threadfence();
        __syncthreads();
        if (tid == 0) {
            atomicAdd(&g_bar, 1u);
            unsigned need = 256u * (unsigned)(t + 1);
            while (*(volatile unsigned*)&g_bar < need) { }
        }
        __syncthreads();
        __threadfence();
    }
}

// ================= generic bf16 GEMM (batched tail) =================
// MODE 2: tanh(+b1) f32 store; MODE 4: bf16 store
template<int MODE>
__global__ __launch_bounds__(256)
void bf16_gemm_kernel(const __nv_bfloat16* __restrict__ A, const __nv_bfloat16* __restrict__ Bw,
                      void* __restrict__ Cv, int M, int N, int K,
                      const float* __restrict__ b1) {
    constexpr int BM = 128, BN = 128, BK = 32;
    constexpr int AST = 40;
    constexpr int MT = 2, NTc = 8;
    constexpr int STAGE = (BM + BN) * AST;

    __shared__ __nv_bfloat16 sm[2 * STAGE];
    const uint32_t smbase = (uint32_t)__cvta_generic_to_shared(sm);

    const int tid = threadIdx.x;
    const int warp = tid >> 5, lane = tid & 31;
    const int wm = warp >> 1;
    const int wn = warp & 1;
    const int m0 = blockIdx.y * BM, n0 = blockIdx.x * BN;
    const int NIT = K / BK;

    float acc[MT][NTc][4];
    #pragma unroll
    for (int mt = 0; mt < MT; mt++)
        #pragma unroll
        for (int nt = 0; nt < NTc; nt++)
            #pragma unroll
            for (int q = 0; q < 4; q++) acc[mt][nt][q] = 0.f;

    auto load_stage = [&](int it, int buf) {
        const int k0 = it * BK;
        const uint32_t base = smbase + (uint32_t)buf * STAGE * 2;
        #pragma unroll
        for (int c = tid; c < (BM + BN) * 4; c += 256) {
            bool isB = c >= BM * 4;
            int cc = isB ? c - BM * 4 : c;
            int row = cc >> 2, part = cc & 3;
            const __nv_bfloat16* src = isB
                ? (Bw + (size_t)(n0 + row) * K + k0 + part * 8)
                : (A  + (size_t)(m0 + row) * K + k0 + part * 8);
            uint32_t dst = base + (uint32_t)(((isB ? BM + row : row) * AST + part * 8) * 2);
            cp_async16(dst, src);
        }
    };

    load_stage(0, 0);
    cp_commit();

    for (int it = 0; it < NIT; it++) {
        if (it + 1 < NIT) { load_stage(it + 1, (it + 1) & 1); cp_commit(); cp_wait<1>(); }
        else              { cp_wait<0>(); }
        __syncthreads();

        const uint32_t aBase = smbase + (uint32_t)(it & 1) * STAGE * 2;
        const uint32_t bBase = aBase + BM * AST * 2;

        #pragma unroll
        for (int kk = 0; kk < 2; kk++) {
            uint32_t a[MT][4];
            #pragma unroll
            for (int mt = 0; mt < MT; mt++) {
                int row = wm * 32 + mt * 16 + (lane & 15);
                int col = kk * 16 + (lane >> 4) * 8;
                ldm_x4(a[mt][0], a[mt][1], a[mt][2], a[mt][3],
                       aBase + (uint32_t)((row * AST + col) * 2));
            }
            uint32_t b[NTc][2];
            #pragma unroll
            for (int ntp = 0; ntp < NTc / 2; ntp++) {
                int row = wn * 64 + ntp * 16 + ((lane >> 4) << 3) + (lane & 7);
                int col = kk * 16 + ((lane >> 3) & 1) * 8;
                ldm_x4(b[2 * ntp][0], b[2 * ntp][1], b[2 * ntp + 1][0], b[2 * ntp + 1][1],
                       bBase + (uint32_t)((row * AST + col) * 2));
            }
            #pragma unroll
            for (int mt = 0; mt < MT; mt++)
                #pragma unroll
                for (int nt = 0; nt < NTc; nt++) {
                    asm volatile(
                        "mma.sync.aligned.m16n8k16.row.col.f32.bf16.bf16.f32 "
                        "{%0,%1,%2,%3}, {%4,%5,%6,%7}, {%8,%9}, {%0,%1,%2,%3};"
                        : "+f"(acc[mt][nt][0]), "+f"(acc[mt][nt][1]),
                          "+f"(acc[mt][nt][2]), "+f"(acc[mt][nt][3])
                        : "r"(a[mt][0]), "r"(a[mt][1]), "r"(a[mt][2]), "r"(a[mt][3]),
                          "r"(b[nt][0]), "r"(b[nt][1]));
                }
        }
        __syncthreads();
    }

    float* Cf = (float*)Cv;
    __nv_bfloat16* Cb = (__nv_bfloat16*)Cv;
    #pragma unroll
    for (int mt = 0; mt < MT; mt++) {
        int r_lo = m0 + wm * 32 + mt * 16 + (lane >> 2);
        int r_hi = r_lo + 8;
        #pragma unroll
        for (int nt = 0; nt < NTc; nt++) {
            int c0 = n0 + wn * 64 + nt * 8 + 2 * (lane & 3);
            float v00 = acc[mt][nt][0], v01 = acc[mt][nt][1];
            float v10 = acc[mt][nt][2], v11 = acc[mt][nt][3];
            if (MODE == 2) {
                float bb0 = b1[c0], bb1 = b1[c0 + 1];
                v00 = tanhf(v00 + bb0); v01 = tanhf(v01 + bb1);
                v10 = tanhf(v10 + bb0); v11 = tanhf(v11 + bb1);
            }
            if (MODE == 4) {
                __nv_bfloat162 lo = __floats2bfloat162_rn(v00, v01);
                __nv_bfloat162 hi = __floats2bfloat162_rn(v10, v11);
                *(__nv_bfloat162*)&Cb[(size_t)r_lo * N + c0] = lo;
                *(__nv_bfloat162*)&Cb[(size_t)r_hi * N + c0] = hi;
            } else {
                Cf[(size_t)r_lo * N + c0] = v00;
                Cf[(size_t)r_lo * N + c0 + 1] = v01;
                Cf[(size_t)r_hi * N + c0] = v10;
                Cf[(size_t)r_hi * N + c0 + 1] = v11;
            }
        }
    }
}

// ---------------- batched attention over all 32 timesteps ----------------
__global__ __launch_bounds__(256) void attn_all_kernel() {
    __shared__ __nv_bfloat16 hs_s[LLEN * HSZ];
    __shared__ float u_s[HSZ];
    __shared__ float sc[LLEN];
    __shared__ float mask_s[LLEN];

    const int r = blockIdx.x;
    const int j = r / BSZ;
    const int tid = threadIdx.x;
    const int warp = tid >> 5, lane = tid & 31;

    #pragma unroll
    for (int idx = tid; idx < LLEN * HSZ / 8; idx += 256) {
        int l = idx >> 6;
        int c8 = (idx & 63) * 8;
        uint4 v = *(const uint4*)&g_Hs[((size_t)l * NB + r) * HSZ + c8];
        *(uint4*)&hs_s[l * HSZ + c8] = v;
    }
    if (tid < LLEN) mask_s[tid] = g_mask[(j * LLEN + tid) * BSZ + (r % BSZ)];
    __syncthreads();

    for (int t = 0; t < TLEN; t++) {
        const size_t row = (size_t)t * NB + r;
        for (int k = tid; k < HSZ; k += 256)
            u_s[k] = __bfloat162float(g_ubf[row * HSZ + k]);
        __syncthreads();

        for (int l = warp; l < LLEN; l += 8) {
            float s = 0.f;
            for (int k = lane; k < HSZ; k += 32)
                s += __bfloat162float(hs_s[l * HSZ + k]) * u_s[k];
            #pragma unroll
            for (int off = 16; off > 0; off >>= 1) s += __shfl_down_sync(0xffffffffu, s, off);
            if (lane == 0) sc[l] = s + mask_s[l];
        }
        __syncthreads();

        if (warp == 0) {
            float v = sc[lane];
            float mx = v;
            #pragma unroll
            for (int off = 16; off > 0; off >>= 1) mx = fmaxf(mx, __shfl_xor_sync(0xffffffffu, mx, off));
            float e = expf(v - mx);
            float ssum = e;
            #pragma unroll
            for (int off = 16; off > 0; off >>= 1) ssum += __shfl_xor_sync(0xffffffffu, ssum, off);
            sc[lane] = e / ssum;
        }
        __syncthreads();

        __nv_bfloat16* hc = g_hcbf + row * (2 * HSZ);
        #pragma unroll
        for (int kq = 0; kq < 2; kq++) {
            int k = tid + kq * 256;
            float cx = 0.f;
            #pragma unroll
            for (int l = 0; l < LLEN; l++) cx += sc[l] * __bfloat162float(hs_s[l * HSZ + k]);
            hc[HSZ + k] = __float2bfloat16_rn(cx);
        }
        if (tid < 64) {
            uint4 v = *(const uint4*)&g_Hd[row * HSZ + tid * 8];
            *(uint4*)&hc[tid * 8] = v;
        }
        __syncthreads();
    }
}

// ---------------- pool + logits + log-softmax + score over all t ----------------
__global__ __launch_bounds__(256) void pool_score_all_kernel(
    const float* __restrict__ Vw, const float* __restrict__ Vb,
    const int* __restrict__ target, float* __restrict__ out) {
    extern __shared__ float dsm[];
    float* Vw_s = dsm;
    float* m_s  = dsm + ESZ * 132;
    float* lgs  = m_s + ESZ;
    __shared__ float red[2];

    const int b = blockIdx.x;
    const int tid = threadIdx.x;
    const int lane = tid & 31;

    for (int idx = tid; idx < V1SZ * ESZ; idx += 256) {
        int v = idx >> 7, e = idx & 127;
        Vw_s[e * 132 + v] = Vw[(size_t)v * ESZ + e];
    }
    __syncthreads();

    float score = 0.f, act = 1.f;
    for (int t = 0; t < TLEN; t++) {
        if (tid < ESZ) {
            const size_t base = ((size_t)t * NB + b) * ESZ + tid;
            float m = g_fc[base];
            #pragma unroll
            for (int jj = 1; jj < NEXN; jj++)
                m = fmaxf(m, g_fc[base + (size_t)jj * BSZ * ESZ]);
            m_s[tid] = m;
        }
        __syncthreads();

        if (tid < V1SZ) {
            float s = Vb[tid];
            #pragma unroll 8
            for (int e = 0; e < ESZ; e++) s += m_s[e] * Vw_s[e * 132 + tid];
            lgs[tid] = s;
        }
        __syncthreads();

        if (tid < 32) {
            float mx = -1e30f;
            for (int v = lane; v < V1SZ; v += 32) mx = fmaxf(mx, lgs[v]);
            #pragma unroll
            for (int off = 16; off > 0; off >>= 1) mx = fmaxf(mx, __shfl_xor_sync(0xffffffffu, mx, off));
            float ssum = 0.f;
            for (int v = lane; v < V1SZ; v += 32) ssum += expf(lgs[v] - mx);
            #pragma unroll
            for (int off = 16; off > 0; off >>= 1) ssum += __shfl_xor_sync(0xffffffffu, ssum, off);
            if (lane == 0) { red[0] = mx; red[1] = ssum; }
        }
        __syncthreads();

        int tg = target[t * BSZ + b];
        float ls = lgs[tg] - red[0] - logf(red[1]);
        score += ls * act;
        act *= (tg != VSZ) ? 1.f : 0.f;
        __syncthreads();
    }
    if (tid == 0) out[b] = score;
}

// ---------------- host orchestration ----------------
extern "C" void kernel_launch(void* const* d_in, const int* in_sizes, int n_in,
                              void* d_out, int out_size) {
    const int*   inputs  = (const int*)  d_in[0];
    const int*   target  = (const int*)  d_in[1];
    const float* enc_Wih = (const float*)d_in[2];
    const float* enc_Whh = (const float*)d_in[3];
    const float* enc_bih = (const float*)d_in[4];
    const float* enc_bhh = (const float*)d_in[5];
    const float* enc_h0  = (const float*)d_in[6];
    const float* enc_c0  = (const float*)d_in[7];
    const float* dec_Wih = (const float*)d_in[8];
    const float* dec_Whh = (const float*)d_in[9];
    const float* dec_bih = (const float*)d_in[10];
    const float* dec_bhh = (const float*)d_in[11];
    const float* dec_c0  = (const float*)d_in[12];
    const float* W_w     = (const float*)d_in[13];
    const float* W_b     = (const float*)d_in[14];
    const float* V_w     = (const float*)d_in[15];
    const float* V_b     = (const float*)d_in[16];
    const float* A_w     = (const float*)d_in[17];
    float* out = (float*)d_out;

    __nv_bfloat16 *WhhPE_p, *WhhPD_p, *Awb_p, *Wwb_p, *hcbf_p, *Hd_p, *ubf_p;
    float *WihPE_p, *WihPD_p, *ebE_p, *ebD_p, *fc_p;
    cudaGetSymbolAddress((void**)&WhhPE_p, g_WhhPE);
    cudaGetSymbolAddress((void**)&WhhPD_p, g_WhhPD);
    cudaGetSymbolAddress((void**)&WihPE_p, g_WihPE);
    cudaGetSymbolAddress((void**)&WihPD_p, g_WihPD);
    cudaGetSymbolAddress((void**)&ebE_p, g_ebE);
    cudaGetSymbolAddress((void**)&ebD_p, g_ebD);
    cudaGetSymbolAddress((void**)&Awb_p, g_Awb);
    cudaGetSymbolAddress((void**)&Wwb_p, g_Wwb);
    cudaGetSymbolAddress((void**)&hcbf_p, g_hcbf);
    cudaGetSymbolAddress((void**)&Hd_p, g_Hd);
    cudaGetSymbolAddress((void**)&ubf_p, g_ubf);
    cudaGetSymbolAddress((void**)&fc_p, g_fc);

    const int ps_smem = (ESZ * 132 + ESZ + 132) * (int)sizeof(float);
    cudaFuncSetAttribute(pool_score_all_kernel, cudaFuncAttributeMaxDynamicSharedMemorySize, ps_smem);
    const int chain_smem = 3 * (128 + 128) * 40 * 2 + 32 * 128 * 4;   // 61440 + 16384 = 77824 B
    cudaFuncSetAttribute(chain_kernel, cudaFuncAttributeMaxDynamicSharedMemorySize, chain_smem);

    // ---- weight prep ----
    permute_lstm_weights_kernel<<<H4SZ, 256>>>(enc_Whh, enc_bih, enc_bhh, enc_Wih,
                                               WhhPE_p, ebE_p, WihPE_p);
    permute_lstm_weights_kernel<<<H4SZ, 256>>>(dec_Whh, dec_bih, dec_bhh, dec_Wih,
                                               WhhPD_p, ebD_p, WihPD_p);
    convert_bf16_kernel<<<(HSZ * HSZ + 255) / 256, 256>>>(A_w, Awb_p, HSZ * HSZ);
    convert_bf16_kernel<<<(ESZ * 2 * HSZ + 255) / 256, 256>>>(W_w, Wwb_p, ESZ * 2 * HSZ);

    // ---- init ----
    init_h_kernel<<<(NB * HSZ + 255) / 256, 256>>>(enc_h0);
    init_mask_kernel<<<(NB + 255) / 256, 256>>>(inputs);

    // ---- persistent LSTM chain: all 64 steps in one launch ----
    chain_kernel<<<dim3(H4SZ / 128, NB / 128), 256, chain_smem>>>(
        inputs, target, enc_c0, dec_c0);

    // ---- batched decoder tail ----
    bf16_gemm_kernel<4><<<dim3(HSZ / 128, NT_ALL / 128), 256>>>(
        Hd_p, Awb_p, (void*)ubf_p, NT_ALL, HSZ, HSZ, nullptr);
    attn_all_kernel<<<NB, 256>>>();
    bf16_gemm_kernel<2><<<dim3(ESZ / 128, NT_ALL / 128), 256>>>(
        hcbf_p, Wwb_p, (void*)fc_p, NT_ALL, ESZ, 2 * HSZ, W_b);
    pool_score_all_kernel<<<BSZ, 256, ps_smem>>>(V_w, V_b, target, out);
}

// round 11
// speedup vs baseline: 1.3948x; 1.0130x over previous
#include <cuda_runtime.h>
#include <cuda_bf16.h>
#include <math.h>
#include <stdint.h>

// ---------------- problem constants ----------------
#define VSZ   128
#define V1SZ  129
#define HSZ   512
#define H4SZ  2048
#define ESZ   128
#define NEXN  4
#define LLEN  32
#define BSZ   512
#define TLEN  32
#define NB    (NEXN * BSZ)      // 2048
#define NT_ALL (TLEN * NB)      // 65536
#define NEGV  (-1e9f)
#define NBH   ((size_t)NB * HSZ)

// ---------------- device scratch (allocation-free) ----------------
__device__ __nv_bfloat16 g_Hs[(size_t)LLEN * NB * HSZ];   // encoder hiddens, time-major
__device__ __nv_bfloat16 g_Hd[(size_t)TLEN * NB * HSZ];   // decoder hiddens, time-major
__device__ __nv_bfloat16 g_hbf[NB * HSZ];                 // h input for t=0
__device__ __nv_bfloat16 g_ubf[(size_t)NT_ALL * HSZ];
__device__ __nv_bfloat16 g_hcbf[(size_t)NT_ALL * 2 * HSZ];
__device__ float g_fc[(size_t)NT_ALL * ESZ];
__device__ float g_mask[NEXN * LLEN * BSZ];
__device__ int   g_idx[NB];
__device__ unsigned int g_bar;
// permuted / converted weights
__device__ __nv_bfloat16 g_WhhPE[H4SZ * HSZ];             // gate-interleaved Whh (bf16)
__device__ __nv_bfloat16 g_WhhPD[H4SZ * HSZ];
__device__ float g_WihTE[V1SZ * H4SZ];                    // token-major Wih + bias folded
__device__ float g_WihTD[V1SZ * H4SZ];
__device__ __nv_bfloat16 g_Awb[HSZ * HSZ];
__device__ __nv_bfloat16 g_Wwb[ESZ * 2 * HSZ];

__device__ __forceinline__ float sigmoidf_(float x) { return 1.f / (1.f + expf(-x)); }

// ---------------- ptx helpers ----------------
__device__ __forceinline__ void cp_async16(uint32_t dst, const void* src) {
    asm volatile("cp.async.cg.shared.global [%0], [%1], 16;\n" :: "r"(dst), "l"(src));
}
__device__ __forceinline__ void cp_commit() { asm volatile("cp.async.commit_group;\n"); }
template<int N> __device__ __forceinline__ void cp_wait() {
    asm volatile("cp.async.wait_group %0;\n" :: "n"(N));
}
__device__ __forceinline__ void ldm_x4(uint32_t& r0, uint32_t& r1, uint32_t& r2, uint32_t& r3,
                                       uint32_t addr) {
    asm volatile("ldmatrix.sync.aligned.m8n8.x4.shared.b16 {%0,%1,%2,%3}, [%4];"
                 : "=r"(r0), "=r"(r1), "=r"(r2), "=r"(r3) : "r"(addr));
}

// ---------------- weight prep ----------------
__global__ void convert_bf16_kernel(const float* __restrict__ src,
                                    __nv_bfloat16* __restrict__ dst, int n) {
    int i = blockIdx.x * blockDim.x + threadIdx.x;
    if (i < n) dst[i] = __float2bfloat16_rn(src[i]);
}

// gate-interleave permutation of Whh: n' = 4h+gate  <-  orig = gate*H + h
__global__ void permute_whh_kernel(const float* __restrict__ Whh,
                                   __nv_bfloat16* __restrict__ WhhP) {
    int np = blockIdx.x;
    int h = np >> 2, g = np & 3;
    int orig = g * HSZ + h;
    for (int k = threadIdx.x; k < HSZ; k += 256)
        WhhP[np * HSZ + k] = __float2bfloat16_rn(Whh[(size_t)orig * HSZ + k]);
}

// token-major Wih with bias folded: WihT[v][np] = Wih[orig(np)][v] + bih[orig] + bhh[orig]
__global__ void transpose_wih_kernel(const float* __restrict__ Wih,
                                     const float* __restrict__ bih,
                                     const float* __restrict__ bhh,
                                     float* __restrict__ WihT) {
    int v = blockIdx.x;                    // 0..128
    for (int np = threadIdx.x; np < H4SZ; np += 256) {
        int h = np >> 2, g = np & 3;
        int orig = g * HSZ + h;
        WihT[(size_t)v * H4SZ + np] = Wih[(size_t)orig * V1SZ + v] + bih[orig] + bhh[orig];
    }
}

// ---------------- init kernels ----------------
__global__ void init_h_kernel(const float* __restrict__ h0) {
    int idx = blockIdx.x * blockDim.x + threadIdx.x;
    if (idx < NB * HSZ) g_hbf[idx] = __float2bfloat16_rn(h0[idx & (HSZ - 1)]);
}

__global__ void init_mask_kernel(const int* __restrict__ inputs) {
    int r = blockIdx.x * blockDim.x + threadIdx.x;
    if (r == 0) g_bar = 0u;
    if (r < NB) {
        int j = r / BSZ, b = r % BSZ;
        float a = 1.f;
        int cnt = 0;
        #pragma unroll
        for (int l = 0; l < LLEN; l++) {
            g_mask[(j * LLEN + l) * BSZ + b] = (a > 0.f) ? 0.f : NEGV;
            cnt += (a > 0.f) ? 1 : 0;
            a *= (inputs[(j * LLEN + l) * BSZ + b] != VSZ) ? 1.f : 0.f;
        }
        g_idx[r] = cnt - 1;
    }
}

// ================= persistent fused LSTM chain (mma.sync) =================
// 256 CTAs (16 n-tiles x 16 m-tiles), 2 CTAs/SM, grid barrier between steps.
// CTA 128x128 gate tile, warp tile 32x64, 3-stage cp.async, c tile in SMEM.
// Epilogue: coalesced token-major WihT reads (bias pre-folded).
__global__ __launch_bounds__(256, 2)
void chain_kernel(const int* __restrict__ inputs, const int* __restrict__ target,
                  const float* __restrict__ enc_c0, const float* __restrict__ dec_c0) {
    constexpr int BM = 128, BN = 128, BK = 32, K = HSZ;
    constexpr int AST = 40;
    constexpr int MT = 2, NTc = 8;
    constexpr int STAGE = (BM + BN) * AST;
    constexpr int NSTAGE = 3;
    constexpr int NIT = K / BK;                   // 16

    extern __shared__ __nv_bfloat16 smd[];
    float* c_s = (float*)(smd + NSTAGE * STAGE);  // [32 h][128 rows]
    const uint32_t smbase = (uint32_t)__cvta_generic_to_shared(smd);

    const int tid = threadIdx.x;
    const int warp = tid >> 5, lane = tid & 31;
    const int wm = warp >> 1;
    const int wn = warp & 1;
    const int m0 = blockIdx.y * BM, n0 = blockIdx.x * BN;
    const unsigned FULL = 0xffffffffu;

    for (int i = tid; i < 32 * 128; i += 256)
        c_s[i] = enc_c0[blockIdx.x * 32 + (i >> 7)];
    __syncthreads();

    for (int t = 0; t < LLEN + TLEN; t++) {
        const bool enc = t < LLEN;
        const __nv_bfloat16* Bw = enc ? g_WhhPE : g_WhhPD;
        const float* WihT = enc ? g_WihTE : g_WihTD;
        const __nv_bfloat16* A;
        int gather = 0;
        if (t == 0)            A = g_hbf;
        else if (t < LLEN)     A = g_Hs + (size_t)(t - 1) * NBH;
        else if (t == LLEN)  { A = g_Hs; gather = 1; }
        else                   A = g_Hd + (size_t)(t - LLEN - 1) * NBH;
        __nv_bfloat16* Hout = enc ? (g_Hs + (size_t)t * NBH)
                                  : (g_Hd + (size_t)(t - LLEN) * NBH);
        int tokmode; const int* tokp = nullptr;
        if (t < LLEN)      { tokmode = 1; tokp = inputs + t * BSZ; }
        else if (t == LLEN)  tokmode = 0;
        else               { tokmode = 2; tokp = target + (t - LLEN - 1) * BSZ; }

        if (t == LLEN) {      // decoder init: reset c to dec_c0
            for (int i = tid; i < 32 * 128; i += 256)
                c_s[i] = dec_c0[blockIdx.x * 32 + (i >> 7)];
            __syncthreads();
        }

        float acc[MT][NTc][4];
        #pragma unroll
        for (int mt = 0; mt < MT; mt++)
            #pragma unroll
            for (int nt = 0; nt < NTc; nt++)
                #pragma unroll
                for (int q = 0; q < 4; q++) acc[mt][nt][q] = 0.f;

        auto load_stage = [&](int it) {
            const int k0 = it * BK;
            const uint32_t base = smbase + (uint32_t)(it % NSTAGE) * STAGE * 2;
            #pragma unroll
            for (int ii = 0; ii < (BM + BN) * 4 / 256; ii++) {
                int c = tid + ii * 256;
                bool isB = c >= BM * 4;
                int cc = isB ? c - BM * 4 : c;
                int row = cc >> 2, part = cc & 3;
                const __nv_bfloat16* src;
                if (isB) {
                    src = Bw + (size_t)(n0 + row) * K + k0 + part * 8;
                } else if (gather) {
                    int rg2 = m0 + row;
                    src = g_Hs + ((size_t)g_idx[rg2] * NB + rg2) * HSZ + k0 + part * 8;
                } else {
                    src = A + (size_t)(m0 + row) * K + k0 + part * 8;
                }
                uint32_t dst = base + (uint32_t)(((isB ? BM + row : row) * AST + part * 8) * 2);
                cp_async16(dst, src);
            }
            cp_commit();
        };

        load_stage(0);
        load_stage(1);

        for (int it = 0; it < NIT; it++) {
            if (it == NIT - 1) cp_wait<0>(); else cp_wait<1>();
            __syncthreads();
            if (it + 2 < NIT) load_stage(it + 2);

            const uint32_t aBase = smbase + (uint32_t)(it % NSTAGE) * STAGE * 2;
            const uint32_t bBase = aBase + BM * AST * 2;

            #pragma unroll
            for (int kk = 0; kk < 2; kk++) {
                uint32_t a[MT][4];
                #pragma unroll
                for (int mt = 0; mt < MT; mt++) {
                    int row = wm * 32 + mt * 16 + (lane & 15);
                    int col = kk * 16 + (lane >> 4) * 8;
                    ldm_x4(a[mt][0], a[mt][1], a[mt][2], a[mt][3],
                           aBase + (uint32_t)((row * AST + col) * 2));
                }
                uint32_t b[NTc][2];
                #pragma unroll
                for (int ntp = 0; ntp < NTc / 2; ntp++) {
                    int row = wn * 64 + ntp * 16 + ((lane >> 4) << 3) + (lane & 7);
                    int col = kk * 16 + ((lane >> 3) & 1) * 8;
                    ldm_x4(b[2 * ntp][0], b[2 * ntp][1], b[2 * ntp + 1][0], b[2 * ntp + 1][1],
                           bBase + (uint32_t)((row * AST + col) * 2));
                }
                #pragma unroll
                for (int mt = 0; mt < MT; mt++)
                    #pragma unroll
                    for (int nt = 0; nt < NTc; nt++) {
                        asm volatile(
                            "mma.sync.aligned.m16n8k16.row.col.f32.bf16.bf16.f32 "
                            "{%0,%1,%2,%3}, {%4,%5,%6,%7}, {%8,%9}, {%0,%1,%2,%3};"
                            : "+f"(acc[mt][nt][0]), "+f"(acc[mt][nt][1]),
                              "+f"(acc[mt][nt][2]), "+f"(acc[mt][nt][3])
                            : "r"(a[mt][0]), "r"(a[mt][1]), "r"(a[mt][2]), "r"(a[mt][3]),
                              "r"(b[nt][0]), "r"(b[nt][1]));
                    }
            }
            __syncthreads();
        }

        // -------- fused LSTM epilogue: coalesced token-major WihT (bias folded) --------
        #pragma unroll
        for (int mt = 0; mt < MT; mt++) {
            int rl_lo = wm * 32 + mt * 16 + (lane >> 2);
            int rl_hi = rl_lo + 8;
            int r_lo = m0 + rl_lo, r_hi = m0 + rl_hi;
            int tok_lo = VSZ, tok_hi = VSZ;
            if (tokmode == 1) {
                tok_lo = tokp[(r_lo / BSZ) * (LLEN * BSZ) + (r_lo % BSZ)];
                tok_hi = tokp[(r_hi / BSZ) * (LLEN * BSZ) + (r_hi % BSZ)];
            } else if (tokmode == 2) {
                tok_lo = tokp[r_lo % BSZ];
                tok_hi = tokp[r_hi % BSZ];
            }
            const float* wl = WihT + (size_t)tok_lo * H4SZ;
            const float* wh_ = WihT + (size_t)tok_hi * H4SZ;
            #pragma unroll
            for (int nt = 0; nt < NTc; nt++) {
                int c0 = n0 + wn * 64 + nt * 8 + 2 * (lane & 3);
                float2 el = *(const float2*)&wl[c0];
                float2 eh = *(const float2*)&wh_[c0];
                float v00 = acc[mt][nt][0] + el.x;
                float v01 = acc[mt][nt][1] + el.y;
                float v10 = acc[mt][nt][2] + eh.x;
                float v11 = acc[mt][nt][3] + eh.y;
                float p00 = __shfl_xor_sync(FULL, v00, 1);
                float p01 = __shfl_xor_sync(FULL, v01, 1);
                float p10 = __shfl_xor_sync(FULL, v10, 1);
                float p11 = __shfl_xor_sync(FULL, v11, 1);
                if ((lane & 1) == 0) {
                    int hl = wn * 16 + nt * 2 + ((lane & 3) >> 1);
                    int hg = blockIdx.x * 32 + hl;
                    {
                        float cold = c_s[hl * 128 + rl_lo];
                        float c2 = sigmoidf_(v01) * cold + sigmoidf_(v00) * tanhf(p00);
                        float h2 = sigmoidf_(p01) * tanhf(c2);
                        c_s[hl * 128 + rl_lo] = c2;
                        Hout[(size_t)r_lo * HSZ + hg] = __float2bfloat16_rn(h2);
                    }
                    {
                        float cold = c_s[hl * 128 + rl_hi];
                        float c2 = sigmoidf_(v11) * cold + sigmoidf_(v10) * tanhf(p10);
                        float h2 = sigmoidf_(p11) * tanhf(c2);
                        c_s[hl * 128 + rl_hi] = c2;
                        Hout[(size_t)r_hi * HSZ + hg] = __float2bfloat16_rn(h2);
                    }
                }
            }
        }

        // -------- grid barrier --------
        __threadfence();
        __syncthreads();
        if (tid == 0) {
            atomicAdd(&g_bar, 1u);
            unsigned need = 256u * (unsigned)(t + 1);
            while (*(volatile unsigned*)&g_bar < need) { }
        }
        __syncthreads();
        __threadfence();
    }
}

// ================= generic bf16 GEMM (batched tail) =================
// MODE 2: tanh(+b1) f32 store; MODE 4: bf16 store
template<int MODE>
__global__ __launch_bounds__(256)
void bf16_gemm_kernel(const __nv_bfloat16* __restrict__ A, const __nv_bfloat16* __restrict__ Bw,
                      void* __restrict__ Cv, int M, int N, int K,
                      const float* __restrict__ b1) {
    constexpr int BM = 128, BN = 128, BK = 32;
    constexpr int AST = 40;
    constexpr int MT = 2, NTc = 8;
    constexpr int STAGE = (BM + BN) * AST;

    __shared__ __nv_bfloat16 sm[2 * STAGE];
    const uint32_t smbase = (uint32_t)__cvta_generic_to_shared(sm);

    const int tid = threadIdx.x;
    const int warp = tid >> 5, lane = tid & 31;
    const int wm = warp >> 1;
    const int wn = warp & 1;
    const int m0 = blockIdx.y * BM, n0 = blockIdx.x * BN;
    const int NIT = K / BK;

    float acc[MT][NTc][4];
    #pragma unroll
    for (int mt = 0; mt < MT; mt++)
        #pragma unroll
        for (int nt = 0; nt < NTc; nt++)
            #pragma unroll
            for (int q = 0; q < 4; q++) acc[mt][nt][q] = 0.f;

    auto load_stage = [&](int it, int buf) {
        const int k0 = it * BK;
        const uint32_t base = smbase + (uint32_t)buf * STAGE * 2;
        #pragma unroll
        for (int c = tid; c < (BM + BN) * 4; c += 256) {
            bool isB = c >= BM * 4;
            int cc = isB ? c - BM * 4 : c;
            int row = cc >> 2, part = cc & 3;
            const __nv_bfloat16* src = isB
                ? (Bw + (size_t)(n0 + row) * K + k0 + part * 8)
                : (A  + (size_t)(m0 + row) * K + k0 + part * 8);
            uint32_t dst = base + (uint32_t)(((isB ? BM + row : row) * AST + part * 8) * 2);
            cp_async16(dst, src);
        }
    };

    load_stage(0, 0);
    cp_commit();

    for (int it = 0; it < NIT; it++) {
        if (it + 1 < NIT) { load_stage(it + 1, (it + 1) & 1); cp_commit(); cp_wait<1>(); }
        else              { cp_wait<0>(); }
        __syncthreads();

        const uint32_t aBase = smbase + (uint32_t)(it & 1) * STAGE * 2;
        const uint32_t bBase = aBase + BM * AST * 2;

        #pragma unroll
        for (int kk = 0; kk < 2; kk++) {
            uint32_t a[MT][4];
            #pragma unroll
            for (int mt = 0; mt < MT; mt++) {
                int row = wm * 32 + mt * 16 + (lane & 15);
                int col = kk * 16 + (lane >> 4) * 8;
                ldm_x4(a[mt][0], a[mt][1], a[mt][2], a[mt][3],
                       aBase + (uint32_t)((row * AST + col) * 2));
            }
            uint32_t b[NTc][2];
            #pragma unroll
            for (int ntp = 0; ntp < NTc / 2; ntp++) {
                int row = wn * 64 + ntp * 16 + ((lane >> 4) << 3) + (lane & 7);
                int col = kk * 16 + ((lane >> 3) & 1) * 8;
                ldm_x4(b[2 * ntp][0], b[2 * ntp][1], b[2 * ntp + 1][0], b[2 * ntp + 1][1],
                       bBase + (uint32_t)((row * AST + col) * 2));
            }
            #pragma unroll
            for (int mt = 0; mt < MT; mt++)
                #pragma unroll
                for (int nt = 0; nt < NTc; nt++) {
                    asm volatile(
                        "mma.sync.aligned.m16n8k16.row.col.f32.bf16.bf16.f32 "
                        "{%0,%1,%2,%3}, {%4,%5,%6,%7}, {%8,%9}, {%0,%1,%2,%3};"
                        : "+f"(acc[mt][nt][0]), "+f"(acc[mt][nt][1]),
                          "+f"(acc[mt][nt][2]), "+f"(acc[mt][nt][3])
                        : "r"(a[mt][0]), "r"(a[mt][1]), "r"(a[mt][2]), "r"(a[mt][3]),
                          "r"(b[nt][0]), "r"(b[nt][1]));
                }
        }
        __syncthreads();
    }

    float* Cf = (float*)Cv;
    __nv_bfloat16* Cb = (__nv_bfloat16*)Cv;
    #pragma unroll
    for (int mt = 0; mt < MT; mt++) {
        int r_lo = m0 + wm * 32 + mt * 16 + (lane >> 2);
        int r_hi = r_lo + 8;
        #pragma unroll
        for (int nt = 0; nt < NTc; nt++) {
            int c0 = n0 + wn * 64 + nt * 8 + 2 * (lane & 3);
            float v00 = acc[mt][nt][0], v01 = acc[mt][nt][1];
            float v10 = acc[mt][nt][2], v11 = acc[mt][nt][3];
            if (MODE == 2) {
                float bb0 = b1[c0], bb1 = b1[c0 + 1];
                v00 = tanhf(v00 + bb0); v01 = tanhf(v01 + bb1);
                v10 = tanhf(v10 + bb0); v11 = tanhf(v11 + bb1);
            }
            if (MODE == 4) {
                __nv_bfloat162 lo = __floats2bfloat162_rn(v00, v01);
                __nv_bfloat162 hi = __floats2bfloat162_rn(v10, v11);
                *(__nv_bfloat162*)&Cb[(size_t)r_lo * N + c0] = lo;
                *(__nv_bfloat162*)&Cb[(size_t)r_hi * N + c0] = hi;
            } else {
                Cf[(size_t)r_lo * N + c0] = v00;
                Cf[(size_t)r_lo * N + c0 + 1] = v01;
                Cf[(size_t)r_hi * N + c0] = v10;
                Cf[(size_t)r_hi * N + c0 + 1] = v11;
            }
        }
    }
}

// ---------------- batched attention over all 32 timesteps ----------------
__global__ __launch_bounds__(256) void attn_all_kernel() {
    __shared__ __nv_bfloat16 hs_s[LLEN * HSZ];
    __shared__ float u_s[HSZ];
    __shared__ float sc[LLEN];
    __shared__ float mask_s[LLEN];

    const int r = blockIdx.x;
    const int j = r / BSZ;
    const int tid = threadIdx.x;
    const int warp = tid >> 5, lane = tid & 31;

    #pragma unroll
    for (int idx = tid; idx < LLEN * HSZ / 8; idx += 256) {
        int l = idx >> 6;
        int c8 = (idx & 63) * 8;
        uint4 v = *(const uint4*)&g_Hs[((size_t)l * NB + r) * HSZ + c8];
        *(uint4*)&hs_s[l * HSZ + c8] = v;
    }
    if (tid < LLEN) mask_s[tid] = g_mask[(j * LLEN + tid) * BSZ + (r % BSZ)];
    __syncthreads();

    for (int t = 0; t < TLEN; t++) {
        const size_t row = (size_t)t * NB + r;
        for (int k = tid; k < HSZ; k += 256)
            u_s[k] = __bfloat162float(g_ubf[row * HSZ + k]);
        __syncthreads();

        for (int l = warp; l < LLEN; l += 8) {
            float s = 0.f;
            for (int k = lane; k < HSZ; k += 32)
                s += __bfloat162float(hs_s[l * HSZ + k]) * u_s[k];
            #pragma unroll
            for (int off = 16; off > 0; off >>= 1) s += __shfl_down_sync(0xffffffffu, s, off);
            if (lane == 0) sc[l] = s + mask_s[l];
        }
        __syncthreads();

        if (warp == 0) {
            float v = sc[lane];
            float mx = v;
            #pragma unroll
            for (int off = 16; off > 0; off >>= 1) mx = fmaxf(mx, __shfl_xor_sync(0xffffffffu, mx, off));
            float e = expf(v - mx);
            float ssum = e;
            #pragma unroll
            for (int off = 16; off > 0; off >>= 1) ssum += __shfl_xor_sync(0xffffffffu, ssum, off);
            sc[lane] = e / ssum;
        }
        __syncthreads();

        __nv_bfloat16* hc = g_hcbf + row * (2 * HSZ);
        #pragma unroll
        for (int kq = 0; kq < 2; kq++) {
            int k = tid + kq * 256;
            float cx = 0.f;
            #pragma unroll
            for (int l = 0; l < LLEN; l++) cx += sc[l] * __bfloat162float(hs_s[l * HSZ + k]);
            hc[HSZ + k] = __float2bfloat16_rn(cx);
        }
        if (tid < 64) {
            uint4 v = *(const uint4*)&g_Hd[row * HSZ + tid * 8];
            *(uint4*)&hc[tid * 8] = v;
        }
        __syncthreads();
    }
}

// ---------------- pool + logits + log-softmax + score over all t ----------------
__global__ __launch_bounds__(256) void pool_score_all_kernel(
    const float* __restrict__ Vw, const float* __restrict__ Vb,
    const int* __restrict__ target, float* __restrict__ out) {
    extern __shared__ float dsm[];
    float* Vw_s = dsm;
    float* m_s  = dsm + ESZ * 132;
    float* lgs  = m_s + ESZ;
    __shared__ float red[2];

    const int b = blockIdx.x;
    const int tid = threadIdx.x;
    const int lane = tid & 31;

    for (int idx = tid; idx < V1SZ * ESZ; idx += 256) {
        int v = idx >> 7, e = idx & 127;
        Vw_s[e * 132 + v] = Vw[(size_t)v * ESZ + e];
    }
    __syncthreads();

    float score = 0.f, act = 1.f;
    for (int t = 0; t < TLEN; t++) {
        if (tid < ESZ) {
            const size_t base = ((size_t)t * NB + b) * ESZ + tid;
            float m = g_fc[base];
            #pragma unroll
            for (int jj = 1; jj < NEXN; jj++)
                m = fmaxf(m, g_fc[base + (size_t)jj * BSZ * ESZ]);
            m_s[tid] = m;
        }
        __syncthreads();

        if (tid < V1SZ) {
            float s = Vb[tid];
            #pragma unroll 8
            for (int e = 0; e < ESZ; e++) s += m_s[e] * Vw_s[e * 132 + tid];
            lgs[tid] = s;
        }
        __syncthreads();

        if (tid < 32) {
            float mx = -1e30f;
            for (int v = lane; v < V1SZ; v += 32) mx = fmaxf(mx, lgs[v]);
            #pragma unroll
            for (int off = 16; off > 0; off >>= 1) mx = fmaxf(mx, __shfl_xor_sync(0xffffffffu, mx, off));
            float ssum = 0.f;
            for (int v = lane; v < V1SZ; v += 32) ssum += expf(lgs[v] - mx);
            #pragma unroll
            for (int off = 16; off > 0; off >>= 1) ssum += __shfl_xor_sync(0xffffffffu, ssum, off);
            if (lane == 0) { red[0] = mx; red[1] = ssum; }
        }
        __syncthreads();

        int tg = target[t * BSZ + b];
        float ls = lgs[tg] - red[0] - logf(red[1]);
        score += ls * act;
        act *= (tg != VSZ) ? 1.f : 0.f;
        __syncthreads();
    }
    if (tid == 0) out[b] = score;
}

// ---------------- host orchestration ----------------
extern "C" void kernel_launch(void* const* d_in, const int* in_sizes, int n_in,
                              void* d_out, int out_size) {
    const int*   inputs  = (const int*)  d_in[0];
    const int*   target  = (const int*)  d_in[1];
    const float* enc_Wih = (const float*)d_in[2];
    const float* enc_Whh = (const float*)d_in[3];
    const float* enc_bih = (const float*)d_in[4];
    const float* enc_bhh = (const float*)d_in[5];
    const float* enc_h0  = (const float*)d_in[6];
    const float* enc_c0  = (const float*)d_in[7];
    const float* dec_Wih = (const float*)d_in[8];
    const float* dec_Whh = (const float*)d_in[9];
    const float* dec_bih = (const float*)d_in[10];
    const float* dec_bhh = (const float*)d_in[11];
    const float* dec_c0  = (const float*)d_in[12];
    const float* W_w     = (const float*)d_in[13];
    const float* W_b     = (const float*)d_in[14];
    const float* V_w     = (const float*)d_in[15];
    const float* V_b     = (const float*)d_in[16];
    const float* A_w     = (const float*)d_in[17];
    float* out = (float*)d_out;

    __nv_bfloat16 *WhhPE_p, *WhhPD_p, *Awb_p, *Wwb_p, *hcbf_p, *Hd_p, *ubf_p;
    float *WihTE_p, *WihTD_p, *fc_p;
    cudaGetSymbolAddress((void**)&WhhPE_p, g_WhhPE);
    cudaGetSymbolAddress((void**)&WhhPD_p, g_WhhPD);
    cudaGetSymbolAddress((void**)&WihTE_p, g_WihTE);
    cudaGetSymbolAddress((void**)&WihTD_p, g_WihTD);
    cudaGetSymbolAddress((void**)&Awb_p, g_Awb);
    cudaGetSymbolAddress((void**)&Wwb_p, g_Wwb);
    cudaGetSymbolAddress((void**)&hcbf_p, g_hcbf);
    cudaGetSymbolAddress((void**)&Hd_p, g_Hd);
    cudaGetSymbolAddress((void**)&ubf_p, g_ubf);
    cudaGetSymbolAddress((void**)&fc_p, g_fc);

    const int ps_smem = (ESZ * 132 + ESZ + 132) * (int)sizeof(float);
    cudaFuncSetAttribute(pool_score_all_kernel, cudaFuncAttributeMaxDynamicSharedMemorySize, ps_smem);
    const int chain_smem = 3 * (128 + 128) * 40 * 2 + 32 * 128 * 4;   // 77824 B
    cudaFuncSetAttribute(chain_kernel, cudaFuncAttributeMaxDynamicSharedMemorySize, chain_smem);

    // ---- weight prep ----
    permute_whh_kernel<<<H4SZ, 256>>>(enc_Whh, WhhPE_p);
    permute_whh_kernel<<<H4SZ, 256>>>(dec_Whh, WhhPD_p);
    transpose_wih_kernel<<<V1SZ, 256>>>(enc_Wih, enc_bih, enc_bhh, WihTE_p);
    transpose_wih_kernel<<<V1SZ, 256>>>(dec_Wih, dec_bih, dec_bhh, WihTD_p);
    convert_bf16_kernel<<<(HSZ * HSZ + 255) / 256, 256>>>(A_w, Awb_p, HSZ * HSZ);
    convert_bf16_kernel<<<(ESZ * 2 * HSZ + 255) / 256, 256>>>(W_w, Wwb_p, ESZ * 2 * HSZ);

    // ---- init ----
    init_h_kernel<<<(NB * HSZ + 255) / 256, 256>>>(enc_h0);
    init_mask_kernel<<<(NB + 255) / 256, 256>>>(inputs);

    // ---- persistent LSTM chain: all 64 steps in one launch ----
    chain_kernel<<<dim3(H4SZ / 128, NB / 128), 256, chain_smem>>>(
        inputs, target, enc_c0, dec_c0);

    // ---- batched decoder tail ----
    bf16_gemm_kernel<4><<<dim3(HSZ / 128, NT_ALL / 128), 256>>>(
        Hd_p, Awb_p, (void*)ubf_p, NT_ALL, HSZ, HSZ, nullptr);
    attn_all_kernel<<<NB, 256>>>();
    bf16_gemm_kernel<2><<<dim3(ESZ / 128, NT_ALL / 128), 256>>>(
        hcbf_p, Wwb_p, (void*)fc_p, NT_ALL, ESZ, 2 * HSZ, W_b);
    pool_score_all_kernel<<<BSZ, 256, ps_smem>>>(V_w, V_b, target, out);
}

// round 12
// speedup vs baseline: 1.4117x; 1.0121x over previous
#include <cuda_runtime.h>
#include <cuda_bf16.h>
#include <math.h>
#include <stdint.h>

// ---------------- problem constants ----------------
#define VSZ   128
#define V1SZ  129
#define HSZ   512
#define H4SZ  2048
#define ESZ   128
#define NEXN  4
#define LLEN  32
#define BSZ   512
#define TLEN  32
#define NB    (NEXN * BSZ)      // 2048
#define NT_ALL (TLEN * NB)      // 65536
#define NEGV  (-1e9f)
#define NBH   ((size_t)NB * HSZ)

// ---------------- device scratch (allocation-free) ----------------
__device__ __nv_bfloat16 g_Hs[(size_t)LLEN * NB * HSZ];
__device__ __nv_bfloat16 g_Hd[(size_t)TLEN * NB * HSZ];
__device__ __nv_bfloat16 g_hbf[NB * HSZ];
__device__ __nv_bfloat16 g_ubf[(size_t)NT_ALL * HSZ];
__device__ __nv_bfloat16 g_hcbf[(size_t)NT_ALL * 2 * HSZ];
__device__ float g_fc[(size_t)NT_ALL * ESZ];
__device__ float g_mask[NEXN * LLEN * BSZ];
__device__ int   g_idx[NB];
__device__ unsigned int g_bar;
__device__ __nv_bfloat16 g_WhhPE[H4SZ * HSZ];
__device__ __nv_bfloat16 g_WhhPD[H4SZ * HSZ];
__device__ float g_WihTE[V1SZ * H4SZ];
__device__ float g_WihTD[V1SZ * H4SZ];
__device__ __nv_bfloat16 g_Awb[HSZ * HSZ];
__device__ __nv_bfloat16 g_Wwb[ESZ * 2 * HSZ];

__device__ __forceinline__ float sigmoidf_(float x) { return 1.f / (1.f + expf(-x)); }

// ---------------- ptx helpers ----------------
__device__ __forceinline__ void cp_async16(uint32_t dst, const void* src) {
    asm volatile("cp.async.cg.shared.global [%0], [%1], 16;\n" :: "r"(dst), "l"(src));
}
__device__ __forceinline__ void cp_commit() { asm volatile("cp.async.commit_group;\n"); }
template<int N> __device__ __forceinline__ void cp_wait() {
    asm volatile("cp.async.wait_group %0;\n" :: "n"(N));
}
__device__ __forceinline__ void ldm_x4(uint32_t& r0, uint32_t& r1, uint32_t& r2, uint32_t& r3,
                                       uint32_t addr) {
    asm volatile("ldmatrix.sync.aligned.m8n8.x4.shared.b16 {%0,%1,%2,%3}, [%4];"
                 : "=r"(r0), "=r"(r1), "=r"(r2), "=r"(r3) : "r"(addr));
}

// ---------------- prep kernels (order matters: chain must be the 6th launch) ----------------
// gate-interleave permutation of Whh: n' = 4h+gate  <-  orig = gate*H + h
__global__ void permute_whh_kernel(const float* __restrict__ Whh,
                                   __nv_bfloat16* __restrict__ WhhP) {
    int np = blockIdx.x;
    int h = np >> 2, g = np & 3;
    int orig = g * HSZ + h;
    for (int k = threadIdx.x; k < HSZ; k += 256)
        WhhP[np * HSZ + k] = __float2bfloat16_rn(Whh[(size_t)orig * HSZ + k]);
}

// token-major Wih + bias for BOTH enc/dec (blockIdx.y selects)
__global__ void transpose_wih_both_kernel(
    const float* __restrict__ WihE, const float* __restrict__ bihE, const float* __restrict__ bhhE,
    const float* __restrict__ WihD, const float* __restrict__ bihD, const float* __restrict__ bhhD) {
    int v = blockIdx.x;
    const float* Wih = blockIdx.y ? WihD : WihE;
    const float* bih = blockIdx.y ? bihD : bihE;
    const float* bhh = blockIdx.y ? bhhD : bhhE;
    float* WihT = blockIdx.y ? g_WihTD : g_WihTE;
    for (int np = threadIdx.x; np < H4SZ; np += 256) {
        int h = np >> 2, g = np & 3;
        int orig = g * HSZ + h;
        WihT[(size_t)v * H4SZ + np] = Wih[(size_t)orig * V1SZ + v] + bih[orig] + bhh[orig];
    }
}

// convert A_w and W_w to bf16 in one kernel
__global__ void convert_both_kernel(const float* __restrict__ Aw, const float* __restrict__ Ww) {
    int i = blockIdx.x * blockDim.x + threadIdx.x;
    if (i < HSZ * HSZ) g_Awb[i] = __float2bfloat16_rn(Aw[i]);
    if (i < ESZ * 2 * HSZ) g_Wwb[i] = __float2bfloat16_rn(Ww[i]);
}

// init h0 broadcast + mask/idx + barrier reset in one kernel
__global__ void init_all_kernel(const float* __restrict__ h0, const int* __restrict__ inputs) {
    int idx = blockIdx.x * blockDim.x + threadIdx.x;
    if (idx == 0) g_bar = 0u;
    if (idx < NB * HSZ) g_hbf[idx] = __float2bfloat16_rn(h0[idx & (HSZ - 1)]);
    if (idx < NB) {
        int r = idx;
        int j = r / BSZ, b = r % BSZ;
        float a = 1.f;
        int cnt = 0;
        #pragma unroll
        for (int l = 0; l < LLEN; l++) {
            g_mask[(j * LLEN + l) * BSZ + b] = (a > 0.f) ? 0.f : NEGV;
            cnt += (a > 0.f) ? 1 : 0;
            a *= (inputs[(j * LLEN + l) * BSZ + b] != VSZ) ? 1.f : 0.f;
        }
        g_idx[r] = cnt - 1;
    }
}

// ================= persistent fused LSTM chain (mma.sync) =================
// 128 CTAs (16 n-tiles x 8 m-tiles), CTA tile 256x128, 512 threads (16 warps 8x2,
// warp tile 32x64). 3-stage cp.async, single sync per K-iter, c tile in SMEM,
// coalesced token-major WihT epilogue, grid barrier between steps.
__global__ __launch_bounds__(512, 1)
void chain_kernel(const int* __restrict__ inputs, const int* __restrict__ target,
                  const float* __restrict__ enc_c0, const float* __restrict__ dec_c0) {
    constexpr int BM = 256, BN = 128, BK = 32, K = HSZ;
    constexpr int AST = 40;
    constexpr int MT = 2, NTc = 8;
    constexpr int STAGE = (BM + BN) * AST;        // 15360 bf16
    constexpr int NSTAGE = 3;
    constexpr int NIT = K / BK;                   // 16
    constexpr int NCTA = 128;

    extern __shared__ __nv_bfloat16 smd[];
    float* c_s = (float*)(smd + NSTAGE * STAGE);  // [32 h][256 rows] = 32 KB
    const uint32_t smbase = (uint32_t)__cvta_generic_to_shared(smd);

    const int tid = threadIdx.x;
    const int warp = tid >> 5, lane = tid & 31;
    const int wm = warp >> 1;                     // 0..7
    const int wn = warp & 1;                      // 0..1
    const int m0 = blockIdx.y * BM, n0 = blockIdx.x * BN;
    const unsigned FULL = 0xffffffffu;

    for (int i = tid; i < 32 * 256; i += 512)
        c_s[i] = enc_c0[blockIdx.x * 32 + (i >> 8)];
    __syncthreads();

    for (int t = 0; t < LLEN + TLEN; t++) {
        const bool enc = t < LLEN;
        const __nv_bfloat16* Bw = enc ? g_WhhPE : g_WhhPD;
        const float* WihT = enc ? g_WihTE : g_WihTD;
        const __nv_bfloat16* A;
        int gather = 0;
        if (t == 0)            A = g_hbf;
        else if (t < LLEN)     A = g_Hs + (size_t)(t - 1) * NBH;
        else if (t == LLEN)  { A = g_Hs; gather = 1; }
        else                   A = g_Hd + (size_t)(t - LLEN - 1) * NBH;
        __nv_bfloat16* Hout = enc ? (g_Hs + (size_t)t * NBH)
                                  : (g_Hd + (size_t)(t - LLEN) * NBH);
        int tokmode; const int* tokp = nullptr;
        if (t < LLEN)      { tokmode = 1; tokp = inputs + t * BSZ; }
        else if (t == LLEN)  tokmode = 0;
        else               { tokmode = 2; tokp = target + (t - LLEN - 1) * BSZ; }

        if (t == LLEN) {      // decoder init: reset c
            for (int i = tid; i < 32 * 256; i += 512)
                c_s[i] = dec_c0[blockIdx.x * 32 + (i >> 8)];
            __syncthreads();
        }

        float acc[MT][NTc][4];
        #pragma unroll
        for (int mt = 0; mt < MT; mt++)
            #pragma unroll
            for (int nt = 0; nt < NTc; nt++)
                #pragma unroll
                for (int q = 0; q < 4; q++) acc[mt][nt][q] = 0.f;

        auto load_stage = [&](int it) {
            const int k0 = it * BK;
            const uint32_t base = smbase + (uint32_t)(it % NSTAGE) * STAGE * 2;
            #pragma unroll
            for (int ii = 0; ii < (BM + BN) * 4 / 512; ii++) {
                int c = tid + ii * 512;
                bool isB = c >= BM * 4;
                int cc = isB ? c - BM * 4 : c;
                int row = cc >> 2, part = cc & 3;
                const __nv_bfloat16* src;
                if (isB) {
                    src = Bw + (size_t)(n0 + row) * K + k0 + part * 8;
                } else if (gather) {
                    int rg2 = m0 + row;
                    src = g_Hs + ((size_t)g_idx[rg2] * NB + rg2) * HSZ + k0 + part * 8;
                } else {
                    src = A + (size_t)(m0 + row) * K + k0 + part * 8;
                }
                uint32_t dst = base + (uint32_t)(((isB ? BM + row : row) * AST + part * 8) * 2);
                cp_async16(dst, src);
            }
            cp_commit();
        };

        load_stage(0);
        load_stage(1);

        for (int it = 0; it < NIT; it++) {
            if (it == NIT - 1) cp_wait<0>(); else cp_wait<1>();
            __syncthreads();
            if (it + 2 < NIT) load_stage(it + 2);

            const uint32_t aBase = smbase + (uint32_t)(it % NSTAGE) * STAGE * 2;
            const uint32_t bBase = aBase + BM * AST * 2;

            #pragma unroll
            for (int kk = 0; kk < 2; kk++) {
                uint32_t a[MT][4];
                #pragma unroll
                for (int mt = 0; mt < MT; mt++) {
                    int row = wm * 32 + mt * 16 + (lane & 15);
                    int col = kk * 16 + (lane >> 4) * 8;
                    ldm_x4(a[mt][0], a[mt][1], a[mt][2], a[mt][3],
                           aBase + (uint32_t)((row * AST + col) * 2));
                }
                uint32_t b[NTc][2];
                #pragma unroll
                for (int ntp = 0; ntp < NTc / 2; ntp++) {
                    int row = wn * 64 + ntp * 16 + ((lane >> 4) << 3) + (lane & 7);
                    int col = kk * 16 + ((lane >> 3) & 1) * 8;
                    ldm_x4(b[2 * ntp][0], b[2 * ntp][1], b[2 * ntp + 1][0], b[2 * ntp + 1][1],
                           bBase + (uint32_t)((row * AST + col) * 2));
                }
                #pragma unroll
                for (int mt = 0; mt < MT; mt++)
                    #pragma unroll
                    for (int nt = 0; nt < NTc; nt++) {
                        asm volatile(
                            "mma.sync.aligned.m16n8k16.row.col.f32.bf16.bf16.f32 "
                            "{%0,%1,%2,%3}, {%4,%5,%6,%7}, {%8,%9}, {%0,%1,%2,%3};"
                            : "+f"(acc[mt][nt][0]), "+f"(acc[mt][nt][1]),
                              "+f"(acc[mt][nt][2]), "+f"(acc[mt][nt][3])
                            : "r"(a[mt][0]), "r"(a[mt][1]), "r"(a[mt][2]), "r"(a[mt][3]),
                              "r"(b[nt][0]), "r"(b[nt][1]));
                    }
            }
        }
        __syncthreads();   // protect smem stages before next step reuses them

        // -------- fused LSTM epilogue --------
        #pragma unroll
        for (int mt = 0; mt < MT; mt++) {
            int rl_lo = wm * 32 + mt * 16 + (lane >> 2);
            int rl_hi = rl_lo + 8;
            int r_lo = m0 + rl_lo, r_hi = m0 + rl_hi;
            int tok_lo = VSZ, tok_hi = VSZ;
            if (tokmode == 1) {
                tok_lo = tokp[(r_lo / BSZ) * (LLEN * BSZ) + (r_lo % BSZ)];
                tok_hi = tokp[(r_hi / BSZ) * (LLEN * BSZ) + (r_hi % BSZ)];
            } else if (tokmode == 2) {
                tok_lo = tokp[r_lo % BSZ];
                tok_hi = tokp[r_hi % BSZ];
            }
            const float* wl = WihT + (size_t)tok_lo * H4SZ;
            const float* wh_ = WihT + (size_t)tok_hi * H4SZ;
            #pragma unroll
            for (int nt = 0; nt < NTc; nt++) {
                int c0 = n0 + wn * 64 + nt * 8 + 2 * (lane & 3);
                float2 el = *(const float2*)&wl[c0];
                float2 eh = *(const float2*)&wh_[c0];
                float v00 = acc[mt][nt][0] + el.x;
                float v01 = acc[mt][nt][1] + el.y;
                float v10 = acc[mt][nt][2] + eh.x;
                float v11 = acc[mt][nt][3] + eh.y;
                float p00 = __shfl_xor_sync(FULL, v00, 1);
                float p01 = __shfl_xor_sync(FULL, v01, 1);
                float p10 = __shfl_xor_sync(FULL, v10, 1);
                float p11 = __shfl_xor_sync(FULL, v11, 1);
                if ((lane & 1) == 0) {
                    int hl = wn * 16 + nt * 2 + ((lane & 3) >> 1);
                    int hg = blockIdx.x * 32 + hl;
                    {
                        float cold = c_s[hl * 256 + rl_lo];
                        float c2 = sigmoidf_(v01) * cold + sigmoidf_(v00) * tanhf(p00);
                        float h2 = sigmoidf_(p01) * tanhf(c2);
                        c_s[hl * 256 + rl_lo] = c2;
                        Hout[(size_t)r_lo * HSZ + hg] = __float2bfloat16_rn(h2);
                    }
                    {
                        float cold = c_s[hl * 256 + rl_hi];
                        float c2 = sigmoidf_(v11) * cold + sigmoidf_(v10) * tanhf(p10);
                        float h2 = sigmoidf_(p11) * tanhf(c2);
                        c_s[hl * 256 + rl_hi] = c2;
                        Hout[(size_t)r_hi * HSZ + hg] = __float2bfloat16_rn(h2);
                    }
                }
            }
        }

        // -------- grid barrier --------
        __threadfence();
        __syncthreads();
        if (tid == 0) {
            atomicAdd(&g_bar, 1u);
            unsigned need = (unsigned)NCTA * (unsigned)(t + 1);
            while (*(volatile unsigned*)&g_bar < need) { }
        }
        __syncthreads();
        __threadfence();
    }
}

// ================= generic bf16 GEMM (batched tail) =================
// MODE 2: tanh(+b1) f32 store; MODE 4: bf16 store
template<int MODE>
__global__ __launch_bounds__(256)
void bf16_gemm_kernel(const __nv_bfloat16* __restrict__ A, const __nv_bfloat16* __restrict__ Bw,
                      void* __restrict__ Cv, int M, int N, int K,
                      const float* __restrict__ b1) {
    constexpr int BM = 128, BN = 128, BK = 32;
    constexpr int AST = 40;
    constexpr int MT = 2, NTc = 8;
    constexpr int STAGE = (BM + BN) * AST;

    __shared__ __nv_bfloat16 sm[2 * STAGE];
    const uint32_t smbase = (uint32_t)__cvta_generic_to_shared(sm);

    const int tid = threadIdx.x;
    const int warp = tid >> 5, lane = tid & 31;
    const int wm = warp >> 1;
    const int wn = warp & 1;
    const int m0 = blockIdx.y * BM, n0 = blockIdx.x * BN;
    const int NIT = K / BK;

    float acc[MT][NTc][4];
    #pragma unroll
    for (int mt = 0; mt < MT; mt++)
        #pragma unroll
        for (int nt = 0; nt < NTc; nt++)
            #pragma unroll
            for (int q = 0; q < 4; q++) acc[mt][nt][q] = 0.f;

    auto load_stage = [&](int it, int buf) {
        const int k0 = it * BK;
        const uint32_t base = smbase + (uint32_t)buf * STAGE * 2;
        #pragma unroll
        for (int c = tid; c < (BM + BN) * 4; c += 256) {
            bool isB = c >= BM * 4;
            int cc = isB ? c - BM * 4 : c;
            int row = cc >> 2, part = cc & 3;
            const __nv_bfloat16* src = isB
                ? (Bw + (size_t)(n0 + row) * K + k0 + part * 8)
                : (A  + (size_t)(m0 + row) * K + k0 + part * 8);
            uint32_t dst = base + (uint32_t)(((isB ? BM + row : row) * AST + part * 8) * 2);
            cp_async16(dst, src);
        }
    };

    load_stage(0, 0);
    cp_commit();

    for (int it = 0; it < NIT; it++) {
        if (it + 1 < NIT) { load_stage(it + 1, (it + 1) & 1); cp_commit(); cp_wait<1>(); }
        else              { cp_wait<0>(); }
        __syncthreads();

        const uint32_t aBase = smbase + (uint32_t)(it & 1) * STAGE * 2;
        const uint32_t bBase = aBase + BM * AST * 2;

        #pragma unroll
        for (int kk = 0; kk < 2; kk++) {
            uint32_t a[MT][4];
            #pragma unroll
            for (int mt = 0; mt < MT; mt++) {
                int row = wm * 32 + mt * 16 + (lane & 15);
                int col = kk * 16 + (lane >> 4) * 8;
                ldm_x4(a[mt][0], a[mt][1], a[mt][2], a[mt][3],
                       aBase + (uint32_t)((row * AST + col) * 2));
            }
            uint32_t b[NTc][2];
            #pragma unroll
            for (int ntp = 0; ntp < NTc / 2; ntp++) {
                int row = wn * 64 + ntp * 16 + ((lane >> 4) << 3) + (lane & 7);
                int col = kk * 16 + ((lane >> 3) & 1) * 8;
                ldm_x4(b[2 * ntp][0], b[2 * ntp][1], b[2 * ntp + 1][0], b[2 * ntp + 1][1],
                       bBase + (uint32_t)((row * AST + col) * 2));
            }
            #pragma unroll
            for (int mt = 0; mt < MT; mt++)
                #pragma unroll
                for (int nt = 0; nt < NTc; nt++) {
                    asm volatile(
                        "mma.sync.aligned.m16n8k16.row.col.f32.bf16.bf16.f32 "
                        "{%0,%1,%2,%3}, {%4,%5,%6,%7}, {%8,%9}, {%0,%1,%2,%3};"
                        : "+f"(acc[mt][nt][0]), "+f"(acc[mt][nt][1]),
                          "+f"(acc[mt][nt][2]), "+f"(acc[mt][nt][3])
                        : "r"(a[mt][0]), "r"(a[mt][1]), "r"(a[mt][2]), "r"(a[mt][3]),
                          "r"(b[nt][0]), "r"(b[nt][1]));
                }
        }
        __syncthreads();
    }

    float* Cf = (float*)Cv;
    __nv_bfloat16* Cb = (__nv_bfloat16*)Cv;
    #pragma unroll
    for (int mt = 0; mt < MT; mt++) {
        int r_lo = m0 + wm * 32 + mt * 16 + (lane >> 2);
        int r_hi = r_lo + 8;
        #pragma unroll
        for (int nt = 0; nt < NTc; nt++) {
            int c0 = n0 + wn * 64 + nt * 8 + 2 * (lane & 3);
            float v00 = acc[mt][nt][0], v01 = acc[mt][nt][1];
            float v10 = acc[mt][nt][2], v11 = acc[mt][nt][3];
            if (MODE == 2) {
                float bb0 = b1[c0], bb1 = b1[c0 + 1];
                v00 = tanhf(v00 + bb0); v01 = tanhf(v01 + bb1);
                v10 = tanhf(v10 + bb0); v11 = tanhf(v11 + bb1);
            }
            if (MODE == 4) {
                __nv_bfloat162 lo = __floats2bfloat162_rn(v00, v01);
                __nv_bfloat162 hi = __floats2bfloat162_rn(v10, v11);
                *(__nv_bfloat162*)&Cb[(size_t)r_lo * N + c0] = lo;
                *(__nv_bfloat162*)&Cb[(size_t)r_hi * N + c0] = hi;
            } else {
                Cf[(size_t)r_lo * N + c0] = v00;
                Cf[(size_t)r_lo * N + c0 + 1] = v01;
                Cf[(size_t)r_hi * N + c0] = v10;
                Cf[(size_t)r_hi * N + c0 + 1] = v11;
            }
        }
    }
}

// ---------------- batched attention over all 32 timesteps ----------------
__global__ __launch_bounds__(256) void attn_all_kernel() {
    __shared__ __nv_bfloat16 hs_s[LLEN * HSZ];
    __shared__ float u_s[HSZ];
    __shared__ float sc[LLEN];
    __shared__ float mask_s[LLEN];

    const int r = blockIdx.x;
    const int j = r / BSZ;
    const int tid = threadIdx.x;
    const int warp = tid >> 5, lane = tid & 31;

    #pragma unroll
    for (int idx = tid; idx < LLEN * HSZ / 8; idx += 256) {
        int l = idx >> 6;
        int c8 = (idx & 63) * 8;
        uint4 v = *(const uint4*)&g_Hs[((size_t)l * NB + r) * HSZ + c8];
        *(uint4*)&hs_s[l * HSZ + c8] = v;
    }
    if (tid < LLEN) mask_s[tid] = g_mask[(j * LLEN + tid) * BSZ + (r % BSZ)];
    __syncthreads();

    for (int t = 0; t < TLEN; t++) {
        const size_t row = (size_t)t * NB + r;
        for (int k = tid; k < HSZ; k += 256)
            u_s[k] = __bfloat162float(g_ubf[row * HSZ + k]);
        __syncthreads();

        for (int l = warp; l < LLEN; l += 8) {
            float s = 0.f;
            for (int k = lane; k < HSZ; k += 32)
                s += __bfloat162float(hs_s[l * HSZ + k]) * u_s[k];
            #pragma unroll
            for (int off = 16; off > 0; off >>= 1) s += __shfl_down_sync(0xffffffffu, s, off);
            if (lane == 0) sc[l] = s + mask_s[l];
        }
        __syncthreads();

        if (warp == 0) {
            float v = sc[lane];
            float mx = v;
            #pragma unroll
            for (int off = 16; off > 0; off >>= 1) mx = fmaxf(mx, __shfl_xor_sync(0xffffffffu, mx, off));
            float e = expf(v - mx);
            float ssum = e;
            #pragma unroll
            for (int off = 16; off > 0; off >>= 1) ssum += __shfl_xor_sync(0xffffffffu, ssum, off);
            sc[lane] = e / ssum;
        }
        __syncthreads();

        __nv_bfloat16* hc = g_hcbf + row * (2 * HSZ);
        #pragma unroll
        for (int kq = 0; kq < 2; kq++) {
            int k = tid + kq * 256;
            float cx = 0.f;
            #pragma unroll
            for (int l = 0; l < LLEN; l++) cx += sc[l] * __bfloat162float(hs_s[l * HSZ + k]);
            hc[HSZ + k] = __float2bfloat16_rn(cx);
        }
        if (tid < 64) {
            uint4 v = *(const uint4*)&g_Hd[row * HSZ + tid * 8];
            *(uint4*)&hc[tid * 8] = v;
        }
        __syncthreads();
    }
}

// ---------------- pool + logits + log-softmax + score over all t ----------------
__global__ __launch_bounds__(256) void pool_score_all_kernel(
    const float* __restrict__ Vw, const float* __restrict__ Vb,
    const int* __restrict__ target, float* __restrict__ out) {
    extern __shared__ float dsm[];
    float* Vw_s = dsm;
    float* m_s  = dsm + ESZ * 132;
    float* lgs  = m_s + ESZ;
    __shared__ float red[2];

    const int b = blockIdx.x;
    const int tid = threadIdx.x;
    const int lane = tid & 31;

    for (int idx = tid; idx < V1SZ * ESZ; idx += 256) {
        int v = idx >> 7, e = idx & 127;
        Vw_s[e * 132 + v] = Vw[(size_t)v * ESZ + e];
    }
    __syncthreads();

    float score = 0.f, act = 1.f;
    for (int t = 0; t < TLEN; t++) {
        if (tid < ESZ) {
            const size_t base = ((size_t)t * NB + b) * ESZ + tid;
            float m = g_fc[base];
            #pragma unroll
            for (int jj = 1; jj < NEXN; jj++)
                m = fmaxf(m, g_fc[base + (size_t)jj * BSZ * ESZ]);
            m_s[tid] = m;
        }
        __syncthreads();

        if (tid < V1SZ) {
            float s = Vb[tid];
            #pragma unroll 8
            for (int e = 0; e < ESZ; e++) s += m_s[e] * Vw_s[e * 132 + tid];
            lgs[tid] = s;
        }
        __syncthreads();

        if (tid < 32) {
            float mx = -1e30f;
            for (int v = lane; v < V1SZ; v += 32) mx = fmaxf(mx, lgs[v]);
            #pragma unroll
            for (int off = 16; off > 0; off >>= 1) mx = fmaxf(mx, __shfl_xor_sync(0xffffffffu, mx, off));
            float ssum = 0.f;
            for (int v = lane; v < V1SZ; v += 32) ssum += expf(lgs[v] - mx);
            #pragma unroll
            for (int off = 16; off > 0; off >>= 1) ssum += __shfl_xor_sync(0xffffffffu, ssum, off);
            if (lane == 0) { red[0] = mx; red[1] = ssum; }
        }
        __syncthreads();

        int tg = target[t * BSZ + b];
        float ls = lgs[tg] - red[0] - logf(red[1]);
        score += ls * act;
        act *= (tg != VSZ) ? 1.f : 0.f;
        __syncthreads();
    }
    if (tid == 0) out[b] = score;
}

// ---------------- host orchestration ----------------
extern "C" void kernel_launch(void* const* d_in, const int* in_sizes, int n_in,
                              void* d_out, int out_size) {
    const int*   inputs  = (const int*)  d_in[0];
    const int*   target  = (const int*)  d_in[1];
    const float* enc_Wih = (const float*)d_in[2];
    const float* enc_Whh = (const float*)d_in[3];
    const float* enc_bih = (const float*)d_in[4];
    const float* enc_bhh = (const float*)d_in[5];
    const float* enc_h0  = (const float*)d_in[6];
    const float* enc_c0  = (const float*)d_in[7];
    const float* dec_Wih = (const float*)d_in[8];
    const float* dec_Whh = (const float*)d_in[9];
    const float* dec_bih = (const float*)d_in[10];
    const float* dec_bhh = (const float*)d_in[11];
    const float* dec_c0  = (const float*)d_in[12];
    const float* W_w     = (const float*)d_in[13];
    const float* W_b     = (const float*)d_in[14];
    const float* V_w     = (const float*)d_in[15];
    const float* V_b     = (const float*)d_in[16];
    const float* A_w     = (const float*)d_in[17];
    float* out = (float*)d_out;

    __nv_bfloat16 *WhhPE_p, *WhhPD_p, *Awb_p, *Wwb_p, *hcbf_p, *Hd_p, *ubf_p;
    float *fc_p;
    cudaGetSymbolAddress((void**)&WhhPE_p, g_WhhPE);
    cudaGetSymbolAddress((void**)&WhhPD_p, g_WhhPD);
    cudaGetSymbolAddress((void**)&Awb_p, g_Awb);
    cudaGetSymbolAddress((void**)&Wwb_p, g_Wwb);
    cudaGetSymbolAddress((void**)&hcbf_p, g_hcbf);
    cudaGetSymbolAddress((void**)&Hd_p, g_Hd);
    cudaGetSymbolAddress((void**)&ubf_p, g_ubf);
    cudaGetSymbolAddress((void**)&fc_p, g_fc);

    const int ps_smem = (ESZ * 132 + ESZ + 132) * (int)sizeof(float);
    cudaFuncSetAttribute(pool_score_all_kernel, cudaFuncAttributeMaxDynamicSharedMemorySize, ps_smem);
    const int chain_smem = 3 * (256 + 128) * 40 * 2 + 32 * 256 * 4;   // 92160 + 32768 = 124928 B
    cudaFuncSetAttribute(chain_kernel, cudaFuncAttributeMaxDynamicSharedMemorySize, chain_smem);

    // ---- launches 1-5 (chain is #6 -> ncu -s 5 -c 1 captures it) ----
    permute_whh_kernel<<<H4SZ, 256>>>(enc_Whh, WhhPE_p);                               // 1
    permute_whh_kernel<<<H4SZ, 256>>>(dec_Whh, WhhPD_p);                               // 2
    transpose_wih_both_kernel<<<dim3(V1SZ, 2), 256>>>(enc_Wih, enc_bih, enc_bhh,
                                                      dec_Wih, dec_bih, dec_bhh);      // 3
    convert_both_kernel<<<(HSZ * HSZ + 255) / 256, 256>>>(A_w, W_w);                   // 4
    init_all_kernel<<<(NB * HSZ + 255) / 256, 256>>>(enc_h0, inputs);                  // 5

    // ---- persistent LSTM chain (launch #6) ----
    chain_kernel<<<dim3(H4SZ / 128, NB / 256), 512, chain_smem>>>(
        inputs, target, enc_c0, dec_c0);

    // ---- batched decoder tail ----
    bf16_gemm_kernel<4><<<dim3(HSZ / 128, NT_ALL / 128), 256>>>(
        Hd_p, Awb_p, (void*)ubf_p, NT_ALL, HSZ, HSZ, nullptr);
    attn_all_kernel<<<NB, 256>>>();
    bf16_gemm_kernel<2><<<dim3(ESZ / 128, NT_ALL / 128), 256>>>(
        hcbf_p, Wwb_p, (void*)fc_p, NT_ALL, ESZ, 2 * HSZ, W_b);
    pool_score_all_kernel<<<BSZ, 256, ps_smem>>>(V_w, V_b, target, out);
}